// round 2
// baseline (speedup 1.0000x reference)
#include <cuda_runtime.h>
#include <math.h>

// ---------------- problem constants ----------------
#define BB    16
#define L0D   4096
#define IND   8
#define DD    256
#define HD    8
#define DK    32
#define FFD   1024
#define PREDD 24
#define UMAX  64
#define SCALE 0.17677669529663687f  // 1/sqrt(32)

// ---------------- scratch (device globals; no allocs allowed) ----------------
__device__ float g_h  [BB*L0D*DD];
__device__ float g_a  [BB*L0D*DD];
__device__ float g_q  [BB*L0D*DD];
__device__ float g_k  [BB*L0D*DD];
__device__ float g_v  [BB*L0D*DD];
__device__ float g_ctx[BB*L0D*DD];
__device__ float g_mid[BB*L0D*FFD];
__device__ float g_y  [BB*L0D*DD];
__device__ float g_M  [BB*HD*L0D];
__device__ int   g_top[BB*HD*UMAX];
__device__ float g_ctxtop[BB*HD*UMAX*DK];
__device__ float g_vmean[BB*DD];
__device__ float g_wt [3*DD*DD];

// ---------------- embed: h = x @ in_w + in_b + pos ----------------
__global__ void embed_kernel(const float* __restrict__ x, const float* __restrict__ in_w,
                             const float* __restrict__ in_b, const float* __restrict__ pos)
{
    int row = blockIdx.x;            // b*L0 + l
    int d   = threadIdx.x;           // 0..255
    int l   = row & (L0D - 1);
    const float* xr = x + (size_t)row * IND;
    float acc = in_b[d] + pos[(size_t)l * DD + d];
#pragma unroll
    for (int i = 0; i < IND; i++) acc += xr[i] * in_w[i * DD + d];
    g_h[(size_t)row * DD + d] = acc;
}

// ---------------- generic tiled SGEMM: Y = act(X[N,K] @ W[K,M] + bias) ----------------
// 64x64 tile, 256 threads, 4x4 micro-tile. act: 0 = none, 1 = exact GELU.
__global__ void sgemm_kernel(const float* __restrict__ X, const float* __restrict__ W,
                             const float* __restrict__ bias, float* __restrict__ Y,
                             int N, int K, int M, int act)
{
    __shared__ float As[16][65];
    __shared__ float Bs[16][65];
    int tid = threadIdx.x;
    int tx = tid & 15, ty = tid >> 4;
    int col0 = blockIdx.x * 64;
    int row0 = blockIdx.y * 64;
    float acc[4][4] = {};

    for (int k0 = 0; k0 < K; k0 += 16) {
#pragma unroll
        for (int i = 0; i < 4; i++) {
            int e = tid + i * 256;
            int r = e >> 4, kk = e & 15;
            int gr = row0 + r;
            As[kk][r] = (gr < N && (k0 + kk) < K) ? X[(size_t)gr * K + k0 + kk] : 0.f;
            int kk2 = e >> 6, c = e & 63;
            int gc = col0 + c;
            Bs[kk2][c] = (gc < M && (k0 + kk2) < K) ? W[(size_t)(k0 + kk2) * M + gc] : 0.f;
        }
        __syncthreads();
#pragma unroll
        for (int kk = 0; kk < 16; kk++) {
            float av[4], bv[4];
#pragma unroll
            for (int i = 0; i < 4; i++) av[i] = As[kk][ty + i * 16];
#pragma unroll
            for (int j = 0; j < 4; j++) bv[j] = Bs[kk][tx + j * 16];
#pragma unroll
            for (int i = 0; i < 4; i++)
#pragma unroll
                for (int j = 0; j < 4; j++) acc[i][j] += av[i] * bv[j];
        }
        __syncthreads();
    }
#pragma unroll
    for (int i = 0; i < 4; i++) {
        int r = row0 + ty + i * 16;
        if (r >= N) continue;
#pragma unroll
        for (int j = 0; j < 4; j++) {
            int c = col0 + tx + j * 16;
            if (c >= M) continue;
            float vv = acc[i][j] + (bias ? bias[c] : 0.f);
            if (act == 1) vv = 0.5f * vv * (1.0f + erff(vv * 0.70710678118654752f));
            Y[(size_t)r * M + c] = vv;
        }
    }
}

// ---------------- conv1d (k=3, pad=1) as implicit GEMM: y = Avirt[B*L,768] @ Wt[768,256] + cb ----------------
__global__ void convgemm_kernel(const float* __restrict__ Hin, const float* __restrict__ cbias,
                                float* __restrict__ Y, int L)
{
    __shared__ float As[16][65];
    __shared__ float Bs[16][65];
    int tid = threadIdx.x;
    int tx = tid & 15, ty = tid >> 4;
    int col0 = blockIdx.x * 64;
    int row0 = blockIdx.y * 64;
    float acc[4][4] = {};

    for (int k0 = 0; k0 < 768; k0 += 16) {
#pragma unroll
        for (int i = 0; i < 4; i++) {
            int e = tid + i * 256;
            int r = e >> 4, kk = e & 15;
            int gk = k0 + kk;
            int kshift = gk >> 8, ci = gk & 255;
            int gr = row0 + r;
            int b = gr / L, t = gr % L;
            int tt = t + kshift - 1;
            As[kk][r] = (tt >= 0 && tt < L) ? Hin[((size_t)b * L + tt) * DD + ci] : 0.f;
            int kk2 = e >> 6, c = e & 63;
            Bs[kk2][c] = g_wt[(size_t)(k0 + kk2) * DD + col0 + c];
        }
        __syncthreads();
#pragma unroll
        for (int kk = 0; kk < 16; kk++) {
            float av[4], bv[4];
#pragma unroll
            for (int i = 0; i < 4; i++) av[i] = As[kk][ty + i * 16];
#pragma unroll
            for (int j = 0; j < 4; j++) bv[j] = Bs[kk][tx + j * 16];
#pragma unroll
            for (int i = 0; i < 4; i++)
#pragma unroll
                for (int j = 0; j < 4; j++) acc[i][j] += av[i] * bv[j];
        }
        __syncthreads();
    }
#pragma unroll
    for (int i = 0; i < 4; i++) {
        int r = row0 + ty + i * 16;
#pragma unroll
        for (int j = 0; j < 4; j++) {
            int c = col0 + tx + j * 16;
            Y[(size_t)r * DD + c] = acc[i][j] + cbias[c];
        }
    }
}

// Wt[(k*256+ci)*256 + co] = cw[co, ci, k]
__global__ void wtrans_kernel(const float* __restrict__ cw)
{
    int e = blockIdx.x * 256 + threadIdx.x;   // over D*D*3
    int co = e / (DD * 3);
    int rem = e % (DD * 3);
    int ci = rem / 3, k = rem % 3;
    g_wt[((size_t)(k * DD + ci)) * DD + co] = cw[e];
}

// ---------------- sparse scores + M = max - mean over u sampled keys ----------------
__global__ void scoresM_kernel(const int* __restrict__ idx, int u, int L)
{
    int chunks = L >> 8;
    int bh = blockIdx.x / chunks;
    int l0 = (blockIdx.x % chunks) << 8;
    int b = bh >> 3, hh = bh & 7;
    __shared__ float sk[UMAX * DK];
    for (int e = threadIdx.x; e < u * DK; e += 256) {
        int t = e >> 5, j = e & 31;
        sk[e] = g_k[((size_t)b * L + idx[t]) * DD + hh * DK + j];
    }
    __syncthreads();
    int l = l0 + threadIdx.x;
    const float* qr = g_q + ((size_t)b * L + l) * DD + hh * DK;
    float q[DK];
#pragma unroll
    for (int j = 0; j < DK; j++) q[j] = qr[j];
    float mx = -INFINITY, sm = 0.f;
    for (int t = 0; t < u; t++) {
        float dot = 0.f;
#pragma unroll
        for (int j = 0; j < DK; j++) dot += q[j] * sk[t * DK + j];
        dot *= SCALE;
        mx = fmaxf(mx, dot);
        sm += dot;
    }
    g_M[(size_t)bh * L + l] = mx - sm / (float)u;
}

// ---------------- top-u selection per (b,h); ties -> lowest index (lax.top_k) ----------------
__global__ void topk_kernel(int u, int L)
{
    int bh = blockIdx.x;
    __shared__ float sm[L0D];
    __shared__ float rv[256];
    __shared__ int   ri[256];
    int tid = threadIdx.x;
    for (int l = tid; l < L; l += 256) sm[l] = g_M[(size_t)bh * L + l];
    __syncthreads();
    for (int t = 0; t < u; t++) {
        float best = -INFINITY; int bi = 0x7fffffff;
        for (int l = tid; l < L; l += 256) {
            float v = sm[l];
            if (v > best || (v == best && l < bi)) { best = v; bi = l; }
        }
        rv[tid] = best; ri[tid] = bi;
        __syncthreads();
        for (int s = 128; s > 0; s >>= 1) {
            if (tid < s) {
                float v2 = rv[tid + s]; int i2 = ri[tid + s];
                if (v2 > rv[tid] || (v2 == rv[tid] && i2 < ri[tid])) { rv[tid] = v2; ri[tid] = i2; }
            }
            __syncthreads();
        }
        if (tid == 0) { g_top[bh * UMAX + t] = ri[0]; sm[ri[0]] = -INFINITY; }
        __syncthreads();
    }
}

// ---------------- V mean over L per (b,h,dk) ----------------
__global__ void vmean_kernel(int L)
{
    int bh = blockIdx.x;
    int b = bh >> 3, hh = bh & 7;
    int tid = threadIdx.x;
    int d = tid & 31, c = tid >> 5;     // 8 chunks
    int chunk = L >> 3;
    float s = 0.f;
    for (int l = c * chunk; l < (c + 1) * chunk; l++)
        s += g_v[((size_t)b * L + l) * DD + hh * DK + d];
    __shared__ float part[8][DK];
    part[c][d] = s;
    __syncthreads();
    if (tid < DK) {
        float tot = 0.f;
#pragma unroll
        for (int cc = 0; cc < 8; cc++) tot += part[cc][d];
        g_vmean[b * DD + hh * DK + d] = tot / (float)L;
    }
}

// ---------------- dense softmax attention for the u selected queries ----------------
__global__ void attntop_kernel(int u, int L)
{
    int gbt = blockIdx.x;               // bh*u + t
    int bh = gbt / u, t = gbt % u;
    int b = bh >> 3, hh = bh & 7;
    int tid = threadIdx.x;
    __shared__ float sl[L0D];
    __shared__ float sq[DK];
    __shared__ float red[256];
    __shared__ float part[8][DK];

    int qi = g_top[bh * UMAX + t];
    if (tid < DK) sq[tid] = g_q[((size_t)b * L + qi) * DD + hh * DK + tid];
    __syncthreads();

    float lmax = -INFINITY;
    for (int l = tid; l < L; l += 256) {
        const float* kr = g_k + ((size_t)b * L + l) * DD + hh * DK;
        float dot = 0.f;
#pragma unroll
        for (int j = 0; j < DK; j++) dot += sq[j] * kr[j];
        dot *= SCALE;
        sl[l] = dot;
        lmax = fmaxf(lmax, dot);
    }
    red[tid] = lmax;
    __syncthreads();
    for (int s = 128; s > 0; s >>= 1) { if (tid < s) red[tid] = fmaxf(red[tid], red[tid + s]); __syncthreads(); }
    float mx = red[0];
    __syncthreads();

    float lsum = 0.f;
    for (int l = tid; l < L; l += 256) { float p = expf(sl[l] - mx); sl[l] = p; lsum += p; }
    red[tid] = lsum;
    __syncthreads();
    for (int s = 128; s > 0; s >>= 1) { if (tid < s) red[tid] += red[tid + s]; __syncthreads(); }
    float inv = 1.f / red[0];
    __syncthreads();

    int d = tid & 31, c = tid >> 5;
    int chunk = L >> 3;
    float acc = 0.f;
    for (int l = c * chunk; l < (c + 1) * chunk; l++)
        acc += sl[l] * g_v[((size_t)b * L + l) * DD + hh * DK + d];
    part[c][d] = acc;
    __syncthreads();
    if (tid < DK) {
        float tot = 0.f;
#pragma unroll
        for (int cc = 0; cc < 8; cc++) tot += part[cc][d];
        g_ctxtop[((size_t)bh * UMAX + t) * DK + tid] = tot * inv;
    }
}

// ---------------- ctx assembly: broadcast V-mean, scatter top rows ----------------
__global__ void ctxfill_kernel(int L)
{
    int row = blockIdx.x;      // b*L + l
    int b = row / L;
    g_ctx[(size_t)row * DD + threadIdx.x] = g_vmean[b * DD + threadIdx.x];
}

__global__ void ctxscatter_kernel(int u, int L)
{
    int e = blockIdx.x * 256 + threadIdx.x;    // over B*H*u*32
    if (e >= BB * HD * u * DK) return;
    int j = e & 31;
    int rest = e >> 5;
    int t = rest % u;
    int bh = rest / u;
    int b = bh >> 3, hh = bh & 7;
    int l = g_top[bh * UMAX + t];
    g_ctx[((size_t)b * L + l) * DD + hh * DK + j] =
        g_ctxtop[((size_t)bh * UMAX + t) * DK + j];
}

// ---------------- residual + LayerNorm (row = 256 elems) ----------------
__global__ void addln_kernel(const float* __restrict__ A, const float* __restrict__ Bt,
                             const float* __restrict__ g, const float* __restrict__ bb,
                             float* __restrict__ out)
{
    size_t row = blockIdx.x;
    int d = threadIdx.x;
    float x = A[row * DD + d] + Bt[row * DD + d];
    __shared__ float red[256];
    red[d] = x; __syncthreads();
    for (int s = 128; s > 0; s >>= 1) { if (d < s) red[d] += red[d + s]; __syncthreads(); }
    float m = red[0] * (1.f / DD);
    __syncthreads();
    float xm = x - m;
    red[d] = xm * xm; __syncthreads();
    for (int s = 128; s > 0; s >>= 1) { if (d < s) red[d] += red[d + s]; __syncthreads(); }
    float v = red[0] * (1.f / DD);
    out[row * DD + d] = xm * rsqrtf(v + 1e-5f) * g[d] + bb[d];
}

// ---------------- maxpool(2) + ELU (elu monotone => elu(max)) ----------------
__global__ void pool_kernel(int Lnew)
{
    int r = blockIdx.x;            // b*Lnew + j
    int b = r / Lnew, j = r % Lnew;
    int d = threadIdx.x;
    int L = Lnew * 2;
    float y0 = g_y[((size_t)b * L + 2 * j    ) * DD + d];
    float y1 = g_y[((size_t)b * L + 2 * j + 1) * DD + d];
    float m = fmaxf(y0, y1);
    g_h[(size_t)r * DD + d] = (m > 0.f) ? m : expm1f(m);
}

// ---------------- final FC on last position ----------------
__global__ void fc_kernel(const float* __restrict__ fcw, const float* __restrict__ fcb,
                          float* __restrict__ out, int L)
{
    int b = blockIdx.x;
    int p = threadIdx.x;
    if (p >= PREDD) return;
    const float* hr = g_h + ((size_t)b * L + (L - 1)) * DD;
    float acc = fcb[p];
    for (int d = 0; d < DD; d++) acc += hr[d] * fcw[d * PREDD + p];
    out[b * PREDD + p] = acc;
}

// ---------------- host orchestration ----------------
extern "C" void kernel_launch(void* const* d_in, const int* in_sizes, int n_in,
                              void* d_out, int out_size)
{
    const float* x    = (const float*)d_in[0];
    const int*   idx[3] = { (const int*)d_in[1], (const int*)d_in[2], (const int*)d_in[3] };
    int          u[3]   = { in_sizes[1], in_sizes[2], in_sizes[3] };
    const float* in_w = (const float*)d_in[4];
    const float* in_b = (const float*)d_in[5];
    const float* pos  = (const float*)d_in[6];
    const float* qw = (const float*)d_in[7];  const float* qb = (const float*)d_in[8];
    const float* kw = (const float*)d_in[9];  const float* kb = (const float*)d_in[10];
    const float* vw = (const float*)d_in[11]; const float* vb = (const float*)d_in[12];
    const float* ow = (const float*)d_in[13]; const float* ob = (const float*)d_in[14];
    const float* f1w = (const float*)d_in[15]; const float* f1b = (const float*)d_in[16];
    const float* f2w = (const float*)d_in[17]; const float* f2b = (const float*)d_in[18];
    const float* n1g = (const float*)d_in[19]; const float* n1b = (const float*)d_in[20];
    const float* n2g = (const float*)d_in[21]; const float* n2b = (const float*)d_in[22];
    const float* cw  = (const float*)d_in[23]; const float* cb  = (const float*)d_in[24];
    const float* fcw = (const float*)d_in[25]; const float* fcb = (const float*)d_in[26];

    float *h, *a, *q, *k, *v, *ctx, *mid, *y;
    cudaGetSymbolAddress((void**)&h,   g_h);
    cudaGetSymbolAddress((void**)&a,   g_a);
    cudaGetSymbolAddress((void**)&q,   g_q);
    cudaGetSymbolAddress((void**)&k,   g_k);
    cudaGetSymbolAddress((void**)&v,   g_v);
    cudaGetSymbolAddress((void**)&ctx, g_ctx);
    cudaGetSymbolAddress((void**)&mid, g_mid);
    cudaGetSymbolAddress((void**)&y,   g_y);

    // embed
    embed_kernel<<<BB * L0D, 256>>>(x, in_w, in_b, pos);

    int L = L0D;
    for (int i = 0; i < 3; i++) {
        int N = BB * L;
        dim3 blk(256);
        dim3 gD(DD / 64, N / 64);     // M=256
        dim3 gF(FFD / 64, N / 64);    // M=1024

        // Q,K,V projections
        sgemm_kernel<<<gD, blk>>>(h, qw + (size_t)i * DD * DD, qb + i * DD, q, N, DD, DD, 0);
        sgemm_kernel<<<gD, blk>>>(h, kw + (size_t)i * DD * DD, kb + i * DD, k, N, DD, DD, 0);
        sgemm_kernel<<<gD, blk>>>(h, vw + (size_t)i * DD * DD, vb + i * DD, v, N, DD, DD, 0);

        // ProbSparse selection
        scoresM_kernel<<<BB * HD * (L / 256), 256>>>(idx[i], u[i], L);
        topk_kernel<<<BB * HD, 256>>>(u[i], L);
        vmean_kernel<<<BB * HD, 256>>>(L);
        attntop_kernel<<<BB * HD * u[i], 256>>>(u[i], L);

        // ctx assembly + output projection
        ctxfill_kernel<<<N, 256>>>(L);
        ctxscatter_kernel<<<(BB * HD * u[i] * DK + 255) / 256, 256>>>(u[i], L);
        sgemm_kernel<<<gD, blk>>>(ctx, ow + (size_t)i * DD * DD, ob + i * DD, a, N, DD, DD, 0);

        // residual + LN1
        addln_kernel<<<N, 256>>>(h, a, n1g + i * DD, n1b + i * DD, h);

        // FFN
        sgemm_kernel<<<gF, blk>>>(h, f1w + (size_t)i * DD * FFD, f1b + i * FFD, mid, N, DD, FFD, 1);
        sgemm_kernel<<<gD, blk>>>(mid, f2w + (size_t)i * FFD * DD, f2b + i * DD, a, N, FFD, DD, 0);

        // residual + LN2
        addln_kernel<<<N, 256>>>(h, a, n2g + i * DD, n2b + i * DD, h);

        // distill
        if (i < 2) {
            wtrans_kernel<<<(DD * DD * 3) / 256, 256>>>(cw + (size_t)i * DD * DD * 3);
            convgemm_kernel<<<dim3(DD / 64, N / 64), blk>>>(h, cb + i * DD, y, L);
            pool_kernel<<<BB * (L / 2), 256>>>(L / 2);
            L /= 2;
        }
    }

    fc_kernel<<<BB, 32>>>(fcw, fcb, (float*)d_out, L);
}

// round 3
// speedup vs baseline: 3.3763x; 3.3763x over previous
#include <cuda_runtime.h>
#include <math.h>

// ---------------- problem constants ----------------
#define BB    16
#define L0D   4096
#define IND   8
#define DD    256
#define HD    8
#define DK    32
#define FFD   1024
#define PREDD 24
#define UMAX  64
#define SCALE 0.17677669529663687f  // 1/sqrt(32)

// GEMM tile config
#define ASTR 36
#define BSTR 136
#define ASZ (128*ASTR)   // 4608 floats
#define BSZ (32*BSTR)    // 4352 floats
#define SMEMSZ ((2*ASZ + 2*BSZ)*4)

// ---------------- scratch (device globals; no allocs allowed) ----------------
__device__ float g_h  [BB*L0D*DD];
__device__ float g_a  [BB*L0D*DD];
__device__ float g_q  [BB*L0D*DD];
__device__ float g_k  [BB*L0D*DD];
__device__ float g_v  [BB*L0D*DD];
__device__ float g_ctx[BB*L0D*DD];
__device__ float g_mid[BB*L0D*FFD];
__device__ float g_y  [BB*L0D*DD];
__device__ float g_M  [BB*HD*L0D];
__device__ int   g_top[BB*HD*UMAX];
__device__ float g_ctxtop[BB*HD*UMAX*DK];
__device__ float g_vmean[BB*DD];
__device__ float g_wt [3*DD*DD];
__device__ float g_S  [BB*HD*UMAX*L0D];   // attention scores/probs scratch
__device__ float g_hl [BB*DD];            // last-row h
__device__ float g_al [BB*DD];            // last-row attn/ffn out
__device__ float g_midl[BB*FFD];          // last-row ffn mid

__device__ __forceinline__ float tf32f(float x) {
    unsigned u;
    asm("cvt.rna.tf32.f32 %0, %1;" : "=r"(u) : "f"(x));
    return __uint_as_float(u);
}

__device__ __forceinline__ float gelu_f(float v) {
    return 0.5f * v * (1.0f + erff(v * 0.70710678118654752f));
}

// ---------------- embed: h = x @ in_w + in_b + pos ----------------
__global__ void embed_kernel(const float* __restrict__ x, const float* __restrict__ in_w,
                             const float* __restrict__ in_b, const float* __restrict__ pos)
{
    int row = blockIdx.x;            // b*L0 + l
    int d   = threadIdx.x;           // 0..255
    int l   = row & (L0D - 1);
    const float* xr = x + (size_t)row * IND;
    float acc = in_b[d] + pos[(size_t)l * DD + d];
#pragma unroll
    for (int i = 0; i < IND; i++) acc += xr[i] * in_w[i * DD + d];
    g_h[(size_t)row * DD + d] = acc;
}

// ---------------- TF32 tensor-core GEMM: Y = act(X[N,K] @ W[K,M] + bias) ----------------
// 128x128 block tile, BK=32, 8 warps (warp tile 32x64), double buffered.
// CONV=1: X is virtual im2col of Hin[B,L,256] with k=3, pad=1 -> K=768.
template<int CONV>
__global__ __launch_bounds__(256)
void mm_kernel(const float* __restrict__ X, const float* __restrict__ W,
               const float* __restrict__ bias, float* __restrict__ Y,
               int N, int K, int M, int act, int L, int lshift)
{
    extern __shared__ float smem[];
    float* As = smem;            // 2 * ASZ
    float* Bs = smem + 2 * ASZ;  // 2 * BSZ

    int tid  = threadIdx.x;
    int lane = tid & 31, wid = tid >> 5;
    int row0 = blockIdx.y * 128, col0 = blockIdx.x * 128;
    int wr = (wid & 3) * 32;
    int wc = (wid >> 2) * 64;
    int g  = lane >> 2, tg = lane & 3;

    float acc[2][8][4] = {};
    float4 ra[4], rb[4];

    int tiles = K >> 5;

    // ---- tile fetch (global -> regs) ----
    auto FETCH = [&](int kt) {
        int k0 = kt * 32;
#pragma unroll
        for (int i = 0; i < 4; i++) {
            int e = tid + i * 256;
            int r = e >> 3, c = (e & 7) * 4;
            if (!CONV) {
                ra[i] = *(const float4*)(X + (size_t)(row0 + r) * K + k0 + c);
            } else {
                int gk = k0 + c;
                int ksh = gk >> 8, ci = gk & 255;
                int gr = row0 + r;
                int bb2 = gr >> lshift, t = gr & (L - 1);
                int tt = t + ksh - 1;
                if (tt >= 0 && tt < L)
                    ra[i] = *(const float4*)(X + ((size_t)(bb2 << lshift) + tt) * DD + ci);
                else
                    ra[i] = make_float4(0.f, 0.f, 0.f, 0.f);
            }
            int r2 = e >> 5, c2 = (e & 31) * 4;
            rb[i] = *(const float4*)(W + (size_t)(k0 + r2) * M + col0 + c2);
        }
    };
    auto STORE = [&](int buf) {
        float* Ab = As + buf * ASZ;
        float* Bb = Bs + buf * BSZ;
#pragma unroll
        for (int i = 0; i < 4; i++) {
            int e = tid + i * 256;
            int r = e >> 3, c = (e & 7) * 4;
            float4 va = ra[i];
            va.x = tf32f(va.x); va.y = tf32f(va.y); va.z = tf32f(va.z); va.w = tf32f(va.w);
            *(float4*)(Ab + r * ASTR + c) = va;
            int r2 = e >> 5, c2 = (e & 31) * 4;
            float4 vb = rb[i];
            vb.x = tf32f(vb.x); vb.y = tf32f(vb.y); vb.z = tf32f(vb.z); vb.w = tf32f(vb.w);
            *(float4*)(Bb + r2 * BSTR + c2) = vb;
        }
    };

    FETCH(0);
    STORE(0);
    __syncthreads();

    for (int kt = 0; kt < tiles; kt++) {
        int cur = kt & 1;
        bool pf = (kt + 1 < tiles);
        if (pf) FETCH(kt + 1);

        const float* Ab = As + cur * ASZ;
        const float* Bb = Bs + cur * BSZ;
#pragma unroll
        for (int ks = 0; ks < 4; ks++) {
            unsigned af[2][4], bf[8][2];
#pragma unroll
            for (int mt = 0; mt < 2; mt++) {
                const float* ap = Ab + (wr + mt * 16 + g) * ASTR + ks * 8 + tg;
                af[mt][0] = __float_as_uint(ap[0]);
                af[mt][1] = __float_as_uint(ap[8 * ASTR]);
                af[mt][2] = __float_as_uint(ap[4]);
                af[mt][3] = __float_as_uint(ap[8 * ASTR + 4]);
            }
#pragma unroll
            for (int nt = 0; nt < 8; nt++) {
                const float* bp = Bb + (ks * 8 + tg) * BSTR + wc + nt * 8 + g;
                bf[nt][0] = __float_as_uint(bp[0]);
                bf[nt][1] = __float_as_uint(bp[4 * BSTR]);
            }
#pragma unroll
            for (int mt = 0; mt < 2; mt++)
#pragma unroll
                for (int nt = 0; nt < 8; nt++) {
                    asm volatile(
                        "mma.sync.aligned.m16n8k8.row.col.f32.tf32.tf32.f32 "
                        "{%0,%1,%2,%3},{%4,%5,%6,%7},{%8,%9},{%0,%1,%2,%3};\n"
                        : "+f"(acc[mt][nt][0]), "+f"(acc[mt][nt][1]),
                          "+f"(acc[mt][nt][2]), "+f"(acc[mt][nt][3])
                        : "r"(af[mt][0]), "r"(af[mt][1]), "r"(af[mt][2]), "r"(af[mt][3]),
                          "r"(bf[nt][0]), "r"(bf[nt][1]));
                }
        }
        if (pf) STORE(cur ^ 1);
        __syncthreads();
    }

    // ---- epilogue ----
#pragma unroll
    for (int mt = 0; mt < 2; mt++) {
#pragma unroll
        for (int nt = 0; nt < 8; nt++) {
            int r = row0 + wr + mt * 16 + g;
            int c = col0 + wc + nt * 8 + 2 * tg;
            float b0 = bias[c], b1 = bias[c + 1];
            float v0 = acc[mt][nt][0] + b0;
            float v1 = acc[mt][nt][1] + b1;
            float v2 = acc[mt][nt][2] + b0;
            float v3 = acc[mt][nt][3] + b1;
            if (act == 1) { v0 = gelu_f(v0); v1 = gelu_f(v1); v2 = gelu_f(v2); v3 = gelu_f(v3); }
            *(float2*)(Y + (size_t)r * M + c)       = make_float2(v0, v1);
            *(float2*)(Y + (size_t)(r + 8) * M + c) = make_float2(v2, v3);
        }
    }
}

// Wt[(k*256+ci)*256 + co] = cw[co, ci, k]
__global__ void wtrans_kernel(const float* __restrict__ cw)
{
    int e = blockIdx.x * 256 + threadIdx.x;   // over D*D*3
    int co = e / (DD * 3);
    int rem = e % (DD * 3);
    int ci = rem / 3, k = rem % 3;
    g_wt[((size_t)(k * DD + ci)) * DD + co] = cw[e];
}

// ---------------- sparse scores + M = max - mean over u sampled keys ----------------
__global__ void scoresM_kernel(const int* __restrict__ idx, int u, int L)
{
    int chunks = L >> 8;
    int bh = blockIdx.x / chunks;
    int l0 = (blockIdx.x % chunks) << 8;
    int b = bh >> 3, hh = bh & 7;
    __shared__ float sk[UMAX * DK];
    for (int e = threadIdx.x; e < u * DK; e += 256) {
        int t = e >> 5, j = e & 31;
        sk[e] = g_k[((size_t)b * L + idx[t]) * DD + hh * DK + j];
    }
    __syncthreads();
    int l = l0 + threadIdx.x;
    const float* qr = g_q + ((size_t)b * L + l) * DD + hh * DK;
    float q[DK];
#pragma unroll
    for (int j = 0; j < DK; j++) q[j] = qr[j];
    float mx = -INFINITY, sm = 0.f;
    for (int t = 0; t < u; t++) {
        float dot = 0.f;
#pragma unroll
        for (int j = 0; j < DK; j++) dot += q[j] * sk[t * DK + j];
        dot *= SCALE;
        mx = fmaxf(mx, dot);
        sm += dot;
    }
    g_M[(size_t)bh * L + l] = mx - sm / (float)u;
}

// ---------------- top-u selection per (b,h); ties -> lowest index (lax.top_k) ----------------
__global__ void topk_kernel(int u, int L)
{
    int bh = blockIdx.x;
    __shared__ float sm[L0D];
    __shared__ float rv[256];
    __shared__ int   ri[256];
    int tid = threadIdx.x;
    for (int l = tid; l < L; l += 256) sm[l] = g_M[(size_t)bh * L + l];
    __syncthreads();
    for (int t = 0; t < u; t++) {
        float best = -INFINITY; int bi = 0x7fffffff;
        for (int l = tid; l < L; l += 256) {
            float v = sm[l];
            if (v > best || (v == best && l < bi)) { best = v; bi = l; }
        }
        rv[tid] = best; ri[tid] = bi;
        __syncthreads();
        for (int s = 128; s > 0; s >>= 1) {
            if (tid < s) {
                float v2 = rv[tid + s]; int i2 = ri[tid + s];
                if (v2 > rv[tid] || (v2 == rv[tid] && i2 < ri[tid])) { rv[tid] = v2; ri[tid] = i2; }
            }
            __syncthreads();
        }
        if (tid == 0) { g_top[bh * UMAX + t] = ri[0]; sm[ri[0]] = -INFINITY; }
        __syncthreads();
    }
}

// ---------------- V mean over L per (b,h,dk) ----------------
__global__ void vmean_kernel(int L)
{
    int bh = blockIdx.x;
    int b = bh >> 3, hh = bh & 7;
    int tid = threadIdx.x;
    int d = tid & 31, c = tid >> 5;     // 8 chunks
    int chunk = L >> 3;
    float s = 0.f;
    for (int l = c * chunk; l < (c + 1) * chunk; l++)
        s += g_v[((size_t)b * L + l) * DD + hh * DK + d];
    __shared__ float part[8][DK];
    part[c][d] = s;
    __syncthreads();
    if (tid < DK) {
        float tot = 0.f;
#pragma unroll
        for (int cc = 0; cc < 8; cc++) tot += part[cc][d];
        g_vmean[b * DD + hh * DK + d] = tot / (float)L;
    }
}

// ---------------- scores for selected queries: S[bh][t][l] = Qt . K[l] * scale ----------------
__global__ void scores_kernel(int u, int L)
{
    int chunks = L >> 8;
    int bh = blockIdx.x / chunks;
    int l0 = (blockIdx.x % chunks) << 8;
    int b = bh >> 3, hh = bh & 7;
    int tid = threadIdx.x;
    __shared__ float sq[UMAX * DK];
    for (int e = tid; e < u * DK; e += 256) {
        int t = e >> 5, j = e & 31;
        int qi = g_top[bh * UMAX + t];
        sq[e] = g_q[((size_t)b * L + qi) * DD + hh * DK + j];
    }
    __syncthreads();
    int l = l0 + tid;
    const float* kr = g_k + ((size_t)b * L + l) * DD + hh * DK;
    float kv[DK];
#pragma unroll
    for (int j = 0; j < DK; j += 4) {
        float4 f = *(const float4*)(kr + j);
        kv[j] = f.x; kv[j + 1] = f.y; kv[j + 2] = f.z; kv[j + 3] = f.w;
    }
    for (int t = 0; t < u; t++) {
        float dot = 0.f;
#pragma unroll
        for (int j = 0; j < DK; j++) dot += kv[j] * sq[t * DK + j];
        g_S[((size_t)bh * UMAX + t) * L + l] = dot * SCALE;
    }
}

// ---------------- row softmax over L for each (bh, t) ----------------
__global__ void softmax_kernel(int u, int L)
{
    int rowid = blockIdx.x;         // bh*u + t
    int bh = rowid / u, t = rowid % u;
    float* S = g_S + ((size_t)bh * UMAX + t) * L;
    int tid = threadIdx.x;
    __shared__ float red[256];

    float lmax = -INFINITY;
    for (int l = tid; l < L; l += 256) lmax = fmaxf(lmax, S[l]);
    red[tid] = lmax; __syncthreads();
    for (int s = 128; s > 0; s >>= 1) { if (tid < s) red[tid] = fmaxf(red[tid], red[tid + s]); __syncthreads(); }
    float mx = red[0]; __syncthreads();

    float lsum = 0.f;
    for (int l = tid; l < L; l += 256) { float p = expf(S[l] - mx); S[l] = p; lsum += p; }
    red[tid] = lsum; __syncthreads();
    for (int s = 128; s > 0; s >>= 1) { if (tid < s) red[tid] += red[tid + s]; __syncthreads(); }
    float inv = 1.f / red[0]; __syncthreads();

    for (int l = tid; l < L; l += 256) S[l] *= inv;
}

// ---------------- ctx_top = P @ V per (b,h); V chunk loaded to smem once ----------------
#define VSTR 36
__global__ void av_kernel(int u, int L)
{
    int bh = blockIdx.x;
    int b = bh >> 3, hh = bh & 7;
    int tid = threadIdx.x;
    int lane = tid & 31, wid = tid >> 5;
    __shared__ float Vc[128 * VSTR];

    float accv[6] = {0.f, 0.f, 0.f, 0.f, 0.f, 0.f};
    int chunks = L >> 7;

    for (int c0 = 0; c0 < chunks; c0++) {
        // load V chunk [128][32]
#pragma unroll
        for (int i = 0; i < 4; i++) {
            int e = tid + i * 256;
            int r = e >> 3, c = (e & 7) * 4;
            float4 f = *(const float4*)(g_v + ((size_t)b * L + (c0 << 7) + r) * DD + hh * DK + c);
            *(float4*)(Vc + r * VSTR + c) = f;
        }
        __syncthreads();
#pragma unroll
        for (int ti = 0; ti < 6; ti++) {
            int t = wid + ti * 8;
            if (t < u) {
                const float* P = g_S + ((size_t)bh * UMAX + t) * L + (c0 << 7);
#pragma unroll
                for (int i0 = 0; i0 < 128; i0 += 32) {
                    float pl = P[i0 + lane];
#pragma unroll
                    for (int s = 0; s < 32; s++) {
                        float pv = __shfl_sync(0xffffffffu, pl, s);
                        accv[ti] += pv * Vc[(i0 + s) * VSTR + lane];
                    }
                }
            }
        }
        __syncthreads();
    }
#pragma unroll
    for (int ti = 0; ti < 6; ti++) {
        int t = wid + ti * 8;
        if (t < u)
            g_ctxtop[((size_t)bh * UMAX + t) * DK + lane] = accv[ti];
    }
}

// ---------------- ctx assembly: broadcast V-mean, scatter top rows ----------------
__global__ void ctxfill_kernel(int L)
{
    int row = blockIdx.x;      // b*L + l
    int b = row / L;
    g_ctx[(size_t)row * DD + threadIdx.x] = g_vmean[b * DD + threadIdx.x];
}

__global__ void ctxscatter_kernel(int u, int L)
{
    int e = blockIdx.x * 256 + threadIdx.x;    // over B*H*u*32
    if (e >= BB * HD * u * DK) return;
    int j = e & 31;
    int rest = e >> 5;
    int t = rest % u;
    int bh = rest / u;
    int b = bh >> 3, hh = bh & 7;
    int l = g_top[bh * UMAX + t];
    g_ctx[((size_t)b * L + l) * DD + hh * DK + j] =
        g_ctxtop[((size_t)bh * UMAX + t) * DK + j];
}

// ---------------- residual + LayerNorm (row = 256 elems) ----------------
__global__ void addln_kernel(const float* __restrict__ A, const float* __restrict__ Bt,
                             const float* __restrict__ g, const float* __restrict__ bb,
                             float* __restrict__ out)
{
    size_t row = blockIdx.x;
    int d = threadIdx.x;
    float x = A[row * DD + d] + Bt[row * DD + d];
    __shared__ float red[256];
    red[d] = x; __syncthreads();
    for (int s = 128; s > 0; s >>= 1) { if (d < s) red[d] += red[d + s]; __syncthreads(); }
    float m = red[0] * (1.f / DD);
    __syncthreads();
    float xm = x - m;
    red[d] = xm * xm; __syncthreads();
    for (int s = 128; s > 0; s >>= 1) { if (d < s) red[d] += red[d + s]; __syncthreads(); }
    float v = red[0] * (1.f / DD);
    out[row * DD + d] = xm * rsqrtf(v + 1e-5f) * g[d] + bb[d];
}

// last-row variant: A at pitched rows, Bt compact, out compact
__global__ void addln_last(const float* __restrict__ A, size_t pitchA,
                           const float* __restrict__ Bt,
                           const float* __restrict__ g, const float* __restrict__ bb,
                           float* __restrict__ out)
{
    int b = blockIdx.x;
    int d = threadIdx.x;
    float x = A[(size_t)b * pitchA + d] + Bt[(size_t)b * DD + d];
    __shared__ float red[256];
    red[d] = x; __syncthreads();
    for (int s = 128; s > 0; s >>= 1) { if (d < s) red[d] += red[d + s]; __syncthreads(); }
    float m = red[0] * (1.f / DD);
    __syncthreads();
    float xm = x - m;
    red[d] = xm * xm; __syncthreads();
    for (int s = 128; s > 0; s >>= 1) { if (d < s) red[d] += red[d + s]; __syncthreads(); }
    float v = red[0] * (1.f / DD);
    out[(size_t)b * DD + d] = xm * rsqrtf(v + 1e-5f) * g[d] + bb[d];
}

// ---------------- small per-batch-row GEMM (16 rows) ----------------
__global__ void rowgemm_kernel(const float* __restrict__ X, size_t xPitch,
                               const float* __restrict__ W, const float* __restrict__ bias,
                               float* __restrict__ Y, int K, int M, int act)
{
    int b = blockIdx.x;
    __shared__ float xs[FFD];
    const float* xr = X + (size_t)b * xPitch;
    for (int i = threadIdx.x; i < K; i += 256) xs[i] = xr[i];
    __syncthreads();
    for (int c = threadIdx.x; c < M; c += 256) {
        float acc = bias[c];
        for (int kk = 0; kk < K; kk++) acc += xs[kk] * W[(size_t)kk * M + c];
        if (act == 1) acc = gelu_f(acc);
        Y[(size_t)b * M + c] = acc;
    }
}

// ---------------- maxpool(2) + ELU (elu monotone => elu(max)) ----------------
__global__ void pool_kernel(int Lnew)
{
    int r = blockIdx.x;            // b*Lnew + j
    int b = r / Lnew, j = r % Lnew;
    int d = threadIdx.x;
    int L = Lnew * 2;
    float y0 = g_y[((size_t)b * L + 2 * j    ) * DD + d];
    float y1 = g_y[((size_t)b * L + 2 * j + 1) * DD + d];
    float m = fmaxf(y0, y1);
    g_h[(size_t)r * DD + d] = (m > 0.f) ? m : expm1f(m);
}

// ---------------- final FC on last position (reads compact g_hl) ----------------
__global__ void fc_kernel(const float* __restrict__ fcw, const float* __restrict__ fcb,
                          float* __restrict__ out)
{
    int b = blockIdx.x;
    int p = threadIdx.x;
    if (p >= PREDD) return;
    const float* hr = g_hl + (size_t)b * DD;
    float acc = fcb[p];
    for (int d = 0; d < DD; d++) acc += hr[d] * fcw[d * PREDD + p];
    out[b * PREDD + p] = acc;
}

// ---------------- host orchestration ----------------
extern "C" void kernel_launch(void* const* d_in, const int* in_sizes, int n_in,
                              void* d_out, int out_size)
{
    const float* x    = (const float*)d_in[0];
    const int*   idx[3] = { (const int*)d_in[1], (const int*)d_in[2], (const int*)d_in[3] };
    int          u[3]   = { in_sizes[1], in_sizes[2], in_sizes[3] };
    const float* in_w = (const float*)d_in[4];
    const float* in_b = (const float*)d_in[5];
    const float* pos  = (const float*)d_in[6];
    const float* qw = (const float*)d_in[7];  const float* qb = (const float*)d_in[8];
    const float* kw = (const float*)d_in[9];  const float* kb = (const float*)d_in[10];
    const float* vw = (const float*)d_in[11]; const float* vb = (const float*)d_in[12];
    const float* ow = (const float*)d_in[13]; const float* ob = (const float*)d_in[14];
    const float* f1w = (const float*)d_in[15]; const float* f1b = (const float*)d_in[16];
    const float* f2w = (const float*)d_in[17]; const float* f2b = (const float*)d_in[18];
    const float* n1g = (const float*)d_in[19]; const float* n1b = (const float*)d_in[20];
    const float* n2g = (const float*)d_in[21]; const float* n2b = (const float*)d_in[22];
    const float* cw  = (const float*)d_in[23]; const float* cb  = (const float*)d_in[24];
    const float* fcw = (const float*)d_in[25]; const float* fcb = (const float*)d_in[26];

    float *h, *a, *q, *k, *v, *ctx, *mid, *y, *wt, *hl, *al, *midl;
    cudaGetSymbolAddress((void**)&h,    g_h);
    cudaGetSymbolAddress((void**)&a,    g_a);
    cudaGetSymbolAddress((void**)&q,    g_q);
    cudaGetSymbolAddress((void**)&k,    g_k);
    cudaGetSymbolAddress((void**)&v,    g_v);
    cudaGetSymbolAddress((void**)&ctx,  g_ctx);
    cudaGetSymbolAddress((void**)&mid,  g_mid);
    cudaGetSymbolAddress((void**)&y,    g_y);
    cudaGetSymbolAddress((void**)&wt,   g_wt);
    cudaGetSymbolAddress((void**)&hl,   g_hl);
    cudaGetSymbolAddress((void**)&al,   g_al);
    cudaGetSymbolAddress((void**)&midl, g_midl);

    static bool attr_done = false;
    if (!attr_done) {
        cudaFuncSetAttribute((const void*)mm_kernel<0>, cudaFuncAttributeMaxDynamicSharedMemorySize, SMEMSZ);
        cudaFuncSetAttribute((const void*)mm_kernel<1>, cudaFuncAttributeMaxDynamicSharedMemorySize, SMEMSZ);
        attr_done = true;
    }

    // embed
    embed_kernel<<<BB * L0D, 256>>>(x, in_w, in_b, pos);

    int L = L0D;
    for (int i = 0; i < 3; i++) {
        int N = BB * L;
        int lshift = (L == 4096) ? 12 : (L == 2048) ? 11 : 10;
        dim3 blk(256);
        dim3 gD(DD / 128, N / 128);     // M=256
        dim3 gF(FFD / 128, N / 128);    // M=1024

        // Q,K,V projections (tf32)
        mm_kernel<0><<<gD, blk, SMEMSZ>>>(h, qw + (size_t)i * DD * DD, qb + i * DD, q, N, DD, DD, 0, L, lshift);
        mm_kernel<0><<<gD, blk, SMEMSZ>>>(h, kw + (size_t)i * DD * DD, kb + i * DD, k, N, DD, DD, 0, L, lshift);
        mm_kernel<0><<<gD, blk, SMEMSZ>>>(h, vw + (size_t)i * DD * DD, vb + i * DD, v, N, DD, DD, 0, L, lshift);

        // ProbSparse selection
        scoresM_kernel<<<BB * HD * (L / 256), 256>>>(idx[i], u[i], L);
        topk_kernel<<<BB * HD, 256>>>(u[i], L);
        vmean_kernel<<<BB * HD, 256>>>(L);

        // dense attention for top-u queries (batched)
        scores_kernel<<<BB * HD * (L / 256), 256>>>(u[i], L);
        softmax_kernel<<<BB * HD * u[i], 256>>>(u[i], L);
        av_kernel<<<BB * HD, 256>>>(u[i], L);

        // ctx assembly
        ctxfill_kernel<<<N, 256>>>(L);
        ctxscatter_kernel<<<(BB * HD * u[i] * DK + 255) / 256, 256>>>(u[i], L);

        if (i < 2) {
            // full-width O-proj + LN + FFN + LN
            mm_kernel<0><<<gD, blk, SMEMSZ>>>(ctx, ow + (size_t)i * DD * DD, ob + i * DD, a, N, DD, DD, 0, L, lshift);
            addln_kernel<<<N, 256>>>(h, a, n1g + i * DD, n1b + i * DD, h);
            mm_kernel<0><<<gF, blk, SMEMSZ>>>(h, f1w + (size_t)i * DD * FFD, f1b + i * FFD, mid, N, DD, FFD, 1, L, lshift);
            mm_kernel<0><<<gD, blk, SMEMSZ>>>(mid, f2w + (size_t)i * FFD * DD, f2b + i * DD, a, N, FFD, DD, 0, L, lshift);
            addln_kernel<<<N, 256>>>(h, a, n2g + i * DD, n2b + i * DD, h);

            // distill (conv k=3 as implicit tf32 GEMM, K=768) + pool+ELU
            wtrans_kernel<<<(DD * DD * 3) / 256, 256>>>(cw + (size_t)i * DD * DD * 3);
            mm_kernel<1><<<gD, blk, SMEMSZ>>>(h, wt, cb + i * DD, y, N, 768, DD, 0, L, lshift);
            pool_kernel<<<BB * (L / 2), 256>>>(L / 2);
            L /= 2;
        } else {
            // last layer: only the final position of each batch matters downstream
            size_t lastOff = (size_t)(L - 1) * DD;
            size_t pitch = (size_t)L * DD;
            rowgemm_kernel<<<BB, 256>>>(ctx + lastOff, pitch, ow + (size_t)i * DD * DD, ob + i * DD, al, DD, DD, 0);
            addln_last<<<BB, 256>>>(h + lastOff, pitch, al, n1g + i * DD, n1b + i * DD, hl);
            rowgemm_kernel<<<BB, 256>>>(hl, DD, f1w + (size_t)i * DD * FFD, f1b + i * FFD, midl, DD, FFD, 1);
            rowgemm_kernel<<<BB, 256>>>(midl, FFD, f2w + (size_t)i * FFD * DD, f2b + i * DD, al, FFD, DD, 0);
            addln_last<<<BB, 256>>>(hl, DD, al, n2g + i * DD, n2b + i * DD, hl);
        }
    }

    fc_kernel<<<BB, 32>>>(fcw, fcb, (float*)d_out);
}

// round 4
// speedup vs baseline: 3.6390x; 1.0778x over previous
#include <cuda_runtime.h>
#include <math.h>

// ---------------- problem constants ----------------
#define BB    16
#define L0D   4096
#define IND   8
#define DD    256
#define HD    8
#define DK    32
#define FFD   1024
#define PREDD 24
#define UMAX  64
#define QKVP  768
#define SCALE 0.17677669529663687f  // 1/sqrt(32)

// GEMM tile config: 128x128 tile, BK=16, double buffered
#define ASTR 20
#define BSTR 136
#define ASZ (128*ASTR)   // 2560 floats
#define BSZ (16*BSTR)    // 2176 floats
#define SMEMSZ ((ASZ+BSZ)*2*4)   // 37888 bytes < 48KB

// ---------------- scratch (device globals; no allocs allowed) ----------------
__device__ float g_h  [BB*L0D*DD];
__device__ float g_a  [BB*L0D*DD];
__device__ float g_qkv[BB*L0D*QKVP];
__device__ float g_mid[BB*L0D*FFD];
__device__ float g_y  [BB*L0D*DD];
__device__ float g_M  [BB*HD*L0D];
__device__ int   g_top[BB*HD*UMAX];
__device__ float g_dctx[BB*HD*UMAX*DK];
__device__ float g_vmean[BB*DD];
__device__ float g_wt [3*DD*DD];
__device__ float g_wqkv[DD*QKVP];
__device__ float g_bqkv[QKVP];
__device__ long long g_sel8[BB*L0D];      // per (b,l): 8 bytes, one per head: t or -1
__device__ float g_abase[BB*DD];
__device__ float g_ctxl[BB*DD];
__device__ float g_hl [BB*DD];
__device__ float g_al [BB*DD];
__device__ float g_midl[BB*FFD];

__device__ __forceinline__ float tf32f(float x) {
    unsigned u;
    asm("cvt.rna.tf32.f32 %0, %1;" : "=r"(u) : "f"(x));
    return __uint_as_float(u);
}

__device__ __forceinline__ float gelu_f(float v) {
    return 0.5f * v * (1.0f + erff(v * 0.70710678118654752f));
}

// ---------------- embed: h = x @ in_w + in_b + pos ----------------
__global__ void embed_kernel(const float* __restrict__ x, const float* __restrict__ in_w,
                             const float* __restrict__ in_b, const float* __restrict__ pos)
{
    int row = blockIdx.x;            // b*L0 + l
    int d   = threadIdx.x;
    int l   = row & (L0D - 1);
    const float* xr = x + (size_t)row * IND;
    float acc = in_b[d] + pos[(size_t)l * DD + d];
#pragma unroll
    for (int i = 0; i < IND; i++) acc += xr[i] * in_w[i * DD + d];
    g_h[(size_t)row * DD + d] = acc;
}

// ---------------- QKV weight/bias concat: g_wqkv[256][768] ----------------
__global__ void qkvcat_kernel(const float* __restrict__ qw, const float* __restrict__ kw,
                              const float* __restrict__ vw, const float* __restrict__ qb,
                              const float* __restrict__ kb, const float* __restrict__ vb)
{
    int e = blockIdx.x * 256 + threadIdx.x;     // over 256*768
    int k = e / QKVP, c = e % QKVP;
    float w = (c < 256) ? qw[k * DD + c] : (c < 512) ? kw[k * DD + c - 256] : vw[k * DD + c - 512];
    g_wqkv[e] = w;
    if (k == 0) g_bqkv[c] = (c < 256) ? qb[c] : (c < 512) ? kb[c - 256] : vb[c - 512];
}

// ---------------- TF32 tensor-core GEMM: Y = act(X[N,K] @ W[K,M] + bias) ----------------
// 128x128 tile, BK=16, 8 warps, double buffered, target 2 CTAs/SM.
// CONV=1: X is virtual im2col of Hin[B,L,256], k=3, pad=1 -> K=768.
template<int CONV>
__global__ __launch_bounds__(256, 2)
void mm_kernel(const float* __restrict__ X, const float* __restrict__ W,
               const float* __restrict__ bias, float* __restrict__ Y,
               int N, int K, int M, int act, int L, int lshift)
{
    extern __shared__ float smem[];
    float* As = smem;            // 2 * ASZ
    float* Bs = smem + 2 * ASZ;  // 2 * BSZ

    int tid  = threadIdx.x;
    int lane = tid & 31, wid = tid >> 5;
    int row0 = blockIdx.y * 128, col0 = blockIdx.x * 128;
    int wr = (wid & 3) * 32;
    int wc = (wid >> 2) * 64;
    int g  = lane >> 2, tg = lane & 3;

    float acc[2][8][4] = {};
    float4 ra[2], rb[2];

    int tiles = K >> 4;

    auto FETCH = [&](int kt) {
        int k0 = kt * 16;
#pragma unroll
        for (int i = 0; i < 2; i++) {
            int e = tid + i * 256;
            int r = e >> 2, c = (e & 3) * 4;
            if (!CONV) {
                ra[i] = *(const float4*)(X + (size_t)(row0 + r) * K + k0 + c);
            } else {
                int gk = k0 + c;
                int ksh = gk >> 8, ci = gk & 255;
                int gr = row0 + r;
                int b2 = gr >> lshift, t = gr & (L - 1);
                int tt = t + ksh - 1;
                if (tt >= 0 && tt < L)
                    ra[i] = *(const float4*)(X + ((size_t)(b2 << lshift) + tt) * DD + ci);
                else
                    ra[i] = make_float4(0.f, 0.f, 0.f, 0.f);
            }
            int r2 = e >> 5, c2 = (e & 31) * 4;
            rb[i] = *(const float4*)(W + (size_t)(k0 + r2) * M + col0 + c2);
        }
    };
    auto STORE = [&](int buf) {
        float* Ab = As + buf * ASZ;
        float* Bb = Bs + buf * BSZ;
#pragma unroll
        for (int i = 0; i < 2; i++) {
            int e = tid + i * 256;
            int r = e >> 2, c = (e & 3) * 4;
            float4 va = ra[i];
            va.x = tf32f(va.x); va.y = tf32f(va.y); va.z = tf32f(va.z); va.w = tf32f(va.w);
            *(float4*)(Ab + r * ASTR + c) = va;
            int r2 = e >> 5, c2 = (e & 31) * 4;
            float4 vb = rb[i];
            vb.x = tf32f(vb.x); vb.y = tf32f(vb.y); vb.z = tf32f(vb.z); vb.w = tf32f(vb.w);
            *(float4*)(Bb + r2 * BSTR + c2) = vb;
        }
    };

    FETCH(0);
    STORE(0);
    __syncthreads();

    for (int kt = 0; kt < tiles; kt++) {
        int cur = kt & 1;
        bool pf = (kt + 1 < tiles);
        if (pf) FETCH(kt + 1);

        const float* Ab = As + cur * ASZ;
        const float* Bb = Bs + cur * BSZ;
#pragma unroll
        for (int ks = 0; ks < 2; ks++) {
            unsigned af[2][4], bf[8][2];
#pragma unroll
            for (int mt = 0; mt < 2; mt++) {
                const float* ap = Ab + (wr + mt * 16 + g) * ASTR + ks * 8 + tg;
                af[mt][0] = __float_as_uint(ap[0]);
                af[mt][1] = __float_as_uint(ap[8 * ASTR]);
                af[mt][2] = __float_as_uint(ap[4]);
                af[mt][3] = __float_as_uint(ap[8 * ASTR + 4]);
            }
#pragma unroll
            for (int nt = 0; nt < 8; nt++) {
                const float* bp = Bb + (ks * 8 + tg) * BSTR + wc + nt * 8 + g;
                bf[nt][0] = __float_as_uint(bp[0]);
                bf[nt][1] = __float_as_uint(bp[4 * BSTR]);
            }
#pragma unroll
            for (int mt = 0; mt < 2; mt++)
#pragma unroll
                for (int nt = 0; nt < 8; nt++) {
                    asm volatile(
                        "mma.sync.aligned.m16n8k8.row.col.f32.tf32.tf32.f32 "
                        "{%0,%1,%2,%3},{%4,%5,%6,%7},{%8,%9},{%0,%1,%2,%3};\n"
                        : "+f"(acc[mt][nt][0]), "+f"(acc[mt][nt][1]),
                          "+f"(acc[mt][nt][2]), "+f"(acc[mt][nt][3])
                        : "r"(af[mt][0]), "r"(af[mt][1]), "r"(af[mt][2]), "r"(af[mt][3]),
                          "r"(bf[nt][0]), "r"(bf[nt][1]));
                }
        }
        if (pf) STORE(cur ^ 1);
        __syncthreads();
    }

#pragma unroll
    for (int mt = 0; mt < 2; mt++) {
#pragma unroll
        for (int nt = 0; nt < 8; nt++) {
            int r = row0 + wr + mt * 16 + g;
            int c = col0 + wc + nt * 8 + 2 * tg;
            float b0 = bias[c], b1 = bias[c + 1];
            float v0 = acc[mt][nt][0] + b0;
            float v1 = acc[mt][nt][1] + b1;
            float v2 = acc[mt][nt][2] + b0;
            float v3 = acc[mt][nt][3] + b1;
            if (act == 1) { v0 = gelu_f(v0); v1 = gelu_f(v1); v2 = gelu_f(v2); v3 = gelu_f(v3); }
            *(float2*)(Y + (size_t)r * M + c)       = make_float2(v0, v1);
            *(float2*)(Y + (size_t)(r + 8) * M + c) = make_float2(v2, v3);
        }
    }
}

// Wt[(k*256+ci)*256 + co] = cw[co, ci, k]
__global__ void wtrans_kernel(const float* __restrict__ cw)
{
    int e = blockIdx.x * 256 + threadIdx.x;
    int co = e / (DD * 3);
    int rem = e % (DD * 3);
    int ci = rem / 3, k = rem % 3;
    g_wt[((size_t)(k * DD + ci)) * DD + co] = cw[e];
}

// ---------------- sparse scores + M = max - mean over u sampled keys ----------------
__global__ void scoresM_kernel(const int* __restrict__ idx, int u, int L)
{
    int chunks = L >> 8;
    int bh = blockIdx.x / chunks;
    int l0 = (blockIdx.x % chunks) << 8;
    int b = bh >> 3, hh = bh & 7;
    __shared__ float sk[UMAX * DK];
    for (int e = threadIdx.x; e < u * DK; e += 256) {
        int t = e >> 5, j = e & 31;
        sk[e] = g_qkv[((size_t)b * L + idx[t]) * QKVP + 256 + hh * DK + j];
    }
    __syncthreads();
    int l = l0 + threadIdx.x;
    const float* qr = g_qkv + ((size_t)b * L + l) * QKVP + hh * DK;
    float q[DK];
#pragma unroll
    for (int j = 0; j < DK; j++) q[j] = qr[j];
    float mx = -INFINITY, sm = 0.f;
    for (int t = 0; t < u; t++) {
        float dot = 0.f;
#pragma unroll
        for (int j = 0; j < DK; j++) dot += q[j] * sk[t * DK + j];
        dot *= SCALE;
        mx = fmaxf(mx, dot);
        sm += dot;
    }
    g_M[(size_t)bh * L + l] = mx - sm / (float)u;
}

// ---------------- top-u selection per (b,h); ties -> lowest index ----------------
__global__ void topk_kernel(int u, int L)
{
    int bh = blockIdx.x;
    __shared__ float sm[L0D];
    __shared__ float rv[256];
    __shared__ int   ri[256];
    int tid = threadIdx.x;
    for (int l = tid; l < L; l += 256) sm[l] = g_M[(size_t)bh * L + l];
    __syncthreads();
    for (int t = 0; t < u; t++) {
        float best = -INFINITY; int bi = 0x7fffffff;
        for (int l = tid; l < L; l += 256) {
            float v = sm[l];
            if (v > best || (v == best && l < bi)) { best = v; bi = l; }
        }
        rv[tid] = best; ri[tid] = bi;
        __syncthreads();
        for (int s = 128; s > 0; s >>= 1) {
            if (tid < s) {
                float v2 = rv[tid + s]; int i2 = ri[tid + s];
                if (v2 > rv[tid] || (v2 == rv[tid] && i2 < ri[tid])) { rv[tid] = v2; ri[tid] = i2; }
            }
            __syncthreads();
        }
        if (tid == 0) { g_top[bh * UMAX + t] = ri[0]; sm[ri[0]] = -INFINITY; }
        __syncthreads();
    }
}

// ---------------- V mean over L per (b,h,dk) ----------------
__global__ void vmean_kernel(int L)
{
    int bh = blockIdx.x;
    int b = bh >> 3, hh = bh & 7;
    int tid = threadIdx.x;
    int d = tid & 31, c = tid >> 5;
    int chunk = L >> 3;
    float s = 0.f;
    for (int l = c * chunk; l < (c + 1) * chunk; l++)
        s += g_qkv[((size_t)b * L + l) * QKVP + 512 + hh * DK + d];
    __shared__ float part[8][DK];
    part[c][d] = s;
    __syncthreads();
    if (tid < DK) {
        float tot = 0.f;
#pragma unroll
        for (int cc = 0; cc < 8; cc++) tot += part[cc][d];
        g_vmean[b * DD + hh * DK + d] = tot / (float)L;
    }
}

// ---------------- selection table: per (b,l,h) -> t or -1 ----------------
__global__ void seltclr_kernel(int n)
{
    int e = blockIdx.x * 256 + threadIdx.x;
    if (e < n) g_sel8[e] = -1LL;
}

__global__ void seltset_kernel(int u, int L)
{
    int e = blockIdx.x * 256 + threadIdx.x;   // over B*H*u
    if (e >= BB * HD * u) return;
    int t = e % u, bh = e / u;
    int b = bh >> 3, hh = bh & 7;
    int l = g_top[bh * UMAX + t];
    ((signed char*)g_sel8)[((size_t)b * L + l) * 8 + hh] = (signed char)t;
}

// ---------------- flash attention for top-u queries -> dctx = ctx_top - vmean_slice ----------------
#define KSTR 33
__global__ __launch_bounds__(256)
void flash_kernel(int u, int L)
{
    int bh = blockIdx.x;
    int b = bh >> 3, hh = bh & 7;
    int tid = threadIdx.x, lane = tid & 31, wid = tid >> 5;
    __shared__ float sq[48 * 32];
    __shared__ float Ks[128 * KSTR];
    __shared__ float Vs[128 * KSTR];

    for (int e = tid; e < u * 32; e += 256) {
        int t = e >> 5, j = e & 31;
        int qi = g_top[bh * UMAX + t];
        sq[e] = g_qkv[((size_t)b * L + qi) * QKVP + hh * DK + j];
    }

    float m[6], s[6], av[6];
#pragma unroll
    for (int i = 0; i < 6; i++) { m[i] = -INFINITY; s[i] = 0.f; av[i] = 0.f; }

    int chunks = L >> 7;
    for (int c0 = 0; c0 < chunks; c0++) {
        __syncthreads();
#pragma unroll
        for (int i = 0; i < 4; i++) {
            int e = tid + i * 256;
            int r = e >> 3, c = (e & 7) * 4;
            const float* base = g_qkv + ((size_t)b * L + (c0 << 7) + r) * QKVP + hh * DK + c;
            float4 kf = *(const float4*)(base + 256);
            float4 vf = *(const float4*)(base + 512);
            float* kd = Ks + r * KSTR + c;
            kd[0] = kf.x; kd[1] = kf.y; kd[2] = kf.z; kd[3] = kf.w;
            float* vd = Vs + r * KSTR + c;
            vd[0] = vf.x; vd[1] = vf.y; vd[2] = vf.z; vd[3] = vf.w;
        }
        __syncthreads();

#pragma unroll
        for (int ti = 0; ti < 6; ti++) {
            int t = wid + ti * 8;
            if (t >= u) continue;
            float sc[4];
#pragma unroll
            for (int sub = 0; sub < 4; sub++) {
                const float* kr = Ks + (sub * 32 + lane) * KSTR;
                const float* qv = sq + t * 32;
                float dot = 0.f;
#pragma unroll
                for (int j = 0; j < 32; j++) dot += qv[j] * kr[j];
                sc[sub] = dot * SCALE;
            }
            float cm = fmaxf(fmaxf(sc[0], sc[1]), fmaxf(sc[2], sc[3]));
#pragma unroll
            for (int o = 16; o > 0; o >>= 1) cm = fmaxf(cm, __shfl_xor_sync(0xffffffffu, cm, o));
            float mn = fmaxf(m[ti], cm);
            float corr = expf(m[ti] - mn);
            m[ti] = mn;
            float p[4]; float ps = 0.f;
#pragma unroll
            for (int sub = 0; sub < 4; sub++) { p[sub] = expf(sc[sub] - mn); ps += p[sub]; }
#pragma unroll
            for (int o = 16; o > 0; o >>= 1) ps += __shfl_xor_sync(0xffffffffu, ps, o);
            s[ti] = s[ti] * corr + ps;
            float a = av[ti] * corr;
#pragma unroll
            for (int sub = 0; sub < 4; sub++)
#pragma unroll
                for (int kk = 0; kk < 32; kk++) {
                    float pv = __shfl_sync(0xffffffffu, p[sub], kk);
                    a += pv * Vs[(sub * 32 + kk) * KSTR + lane];
                }
            av[ti] = a;
        }
    }

    float vm = g_vmean[b * DD + hh * DK + lane];
#pragma unroll
    for (int ti = 0; ti < 6; ti++) {
        int t = wid + ti * 8;
        if (t < u)
            g_dctx[((size_t)bh * UMAX + t) * DK + lane] = av[ti] / s[ti] - vm;
    }
}

// ---------------- fused residual + attn-base + sparse correction + LayerNorm ----------------
__global__ void addln1f_kernel(const float* __restrict__ h, const float* __restrict__ wo,
                               const float* __restrict__ g, const float* __restrict__ bb,
                               float* __restrict__ out, int L, int lshift)
{
    int row = blockIdx.x;
    int b = row >> lshift, l = row & (L - 1);
    int d = threadIdx.x;
    float x = h[(size_t)row * DD + d] + g_abase[b * DD + d];
    long long sv = g_sel8[(size_t)b * L + l];
    if (sv != -1LL) {
#pragma unroll
        for (int hh = 0; hh < 8; hh++) {
            int t = (int)(signed char)(sv >> (hh * 8));
            if (t >= 0) {
                const float* dc = g_dctx + ((size_t)(b * 8 + hh) * UMAX + t) * DK;
                const float* wr = wo + (size_t)hh * 32 * DD + d;
#pragma unroll
                for (int j = 0; j < 32; j++) x += dc[j] * wr[(size_t)j * DD];
            }
        }
    }
    __shared__ float red[256];
    red[d] = x; __syncthreads();
    for (int st = 128; st > 0; st >>= 1) { if (d < st) red[d] += red[d + st]; __syncthreads(); }
    float mval = red[0] * (1.f / DD);
    __syncthreads();
    float xm = x - mval;
    red[d] = xm * xm; __syncthreads();
    for (int st = 128; st > 0; st >>= 1) { if (d < st) red[d] += red[d + st]; __syncthreads(); }
    float v = red[0] * (1.f / DD);
    out[(size_t)row * DD + d] = xm * rsqrtf(v + 1e-5f) * g[d] + bb[d];
}

// ---------------- residual + LayerNorm ----------------
__global__ void addln_kernel(const float* __restrict__ A, const float* __restrict__ Bt,
                             const float* __restrict__ g, const float* __restrict__ bb,
                             float* __restrict__ out)
{
    size_t row = blockIdx.x;
    int d = threadIdx.x;
    float x = A[row * DD + d] + Bt[row * DD + d];
    __shared__ float red[256];
    red[d] = x; __syncthreads();
    for (int s = 128; s > 0; s >>= 1) { if (d < s) red[d] += red[d + s]; __syncthreads(); }
    float m = red[0] * (1.f / DD);
    __syncthreads();
    float xm = x - m;
    red[d] = xm * xm; __syncthreads();
    for (int s = 128; s > 0; s >>= 1) { if (d < s) red[d] += red[d + s]; __syncthreads(); }
    float v = red[0] * (1.f / DD);
    out[row * DD + d] = xm * rsqrtf(v + 1e-5f) * g[d] + bb[d];
}

// last-row variant
__global__ void addln_last(const float* __restrict__ A, size_t pitchA,
                           const float* __restrict__ Bt,
                           const float* __restrict__ g, const float* __restrict__ bb,
                           float* __restrict__ out)
{
    int b = blockIdx.x;
    int d = threadIdx.x;
    float x = A[(size_t)b * pitchA + d] + Bt[(size_t)b * DD + d];
    __shared__ float red[256];
    red[d] = x; __syncthreads();
    for (int s = 128; s > 0; s >>= 1) { if (d < s) red[d] += red[d + s]; __syncthreads(); }
    float m = red[0] * (1.f / DD);
    __syncthreads();
    float xm = x - m;
    red[d] = xm * xm; __syncthreads();
    for (int s = 128; s > 0; s >>= 1) { if (d < s) red[d] += red[d + s]; __syncthreads(); }
    float v = red[0] * (1.f / DD);
    out[(size_t)b * DD + d] = xm * rsqrtf(v + 1e-5f) * g[d] + bb[d];
}

// ---------------- last-layer ctx row (l = L-1) ----------------
__global__ void ctxlast_kernel(int L)
{
    int b = blockIdx.x, d = threadIdx.x;
    float val = g_vmean[b * DD + d];
    int hh = d >> 5, j = d & 31;
    signed char t = ((const signed char*)g_sel8)[((size_t)b * L + (L - 1)) * 8 + hh];
    if (t >= 0) val += g_dctx[((size_t)(b * 8 + hh) * UMAX + (int)t) * DK + j];
    g_ctxl[b * DD + d] = val;
}

// ---------------- small per-batch-row GEMM (16 rows) ----------------
__global__ void rowgemm_kernel(const float* __restrict__ X, size_t xPitch,
                               const float* __restrict__ W, const float* __restrict__ bias,
                               float* __restrict__ Y, int K, int M, int act)
{
    int b = blockIdx.x;
    __shared__ float xs[FFD];
    const float* xr = X + (size_t)b * xPitch;
    for (int i = threadIdx.x; i < K; i += 256) xs[i] = xr[i];
    __syncthreads();
    for (int c = threadIdx.x; c < M; c += 256) {
        float acc = bias[c];
        for (int kk = 0; kk < K; kk++) acc += xs[kk] * W[(size_t)kk * M + c];
        if (act == 1) acc = gelu_f(acc);
        Y[(size_t)b * M + c] = acc;
    }
}

// ---------------- maxpool(2) + ELU ----------------
__global__ void pool_kernel(int Lnew)
{
    int r = blockIdx.x;
    int b = r / Lnew, j = r % Lnew;
    int d = threadIdx.x;
    int L = Lnew * 2;
    float y0 = g_y[((size_t)b * L + 2 * j    ) * DD + d];
    float y1 = g_y[((size_t)b * L + 2 * j + 1) * DD + d];
    float m = fmaxf(y0, y1);
    g_h[(size_t)r * DD + d] = (m > 0.f) ? m : expm1f(m);
}

// ---------------- final FC ----------------
__global__ void fc_kernel(const float* __restrict__ fcw, const float* __restrict__ fcb,
                          float* __restrict__ out)
{
    int b = blockIdx.x;
    int p = threadIdx.x;
    if (p >= PREDD) return;
    const float* hr = g_hl + (size_t)b * DD;
    float acc = fcb[p];
    for (int d = 0; d < DD; d++) acc += hr[d] * fcw[d * PREDD + p];
    out[b * PREDD + p] = acc;
}

// ---------------- host orchestration ----------------
extern "C" void kernel_launch(void* const* d_in, const int* in_sizes, int n_in,
                              void* d_out, int out_size)
{
    const float* x    = (const float*)d_in[0];
    const int*   idx[3] = { (const int*)d_in[1], (const int*)d_in[2], (const int*)d_in[3] };
    int          u[3]   = { in_sizes[1], in_sizes[2], in_sizes[3] };
    const float* in_w = (const float*)d_in[4];
    const float* in_b = (const float*)d_in[5];
    const float* pos  = (const float*)d_in[6];
    const float* qw = (const float*)d_in[7];  const float* qb = (const float*)d_in[8];
    const float* kw = (const float*)d_in[9];  const float* kb = (const float*)d_in[10];
    const float* vw = (const float*)d_in[11]; const float* vb = (const float*)d_in[12];
    const float* ow = (const float*)d_in[13]; const float* ob = (const float*)d_in[14];
    const float* f1w = (const float*)d_in[15]; const float* f1b = (const float*)d_in[16];
    const float* f2w = (const float*)d_in[17]; const float* f2b = (const float*)d_in[18];
    const float* n1g = (const float*)d_in[19]; const float* n1b = (const float*)d_in[20];
    const float* n2g = (const float*)d_in[21]; const float* n2b = (const float*)d_in[22];
    const float* cw  = (const float*)d_in[23]; const float* cb  = (const float*)d_in[24];
    const float* fcw = (const float*)d_in[25]; const float* fcb = (const float*)d_in[26];

    float *h, *a, *qkv, *mid, *y, *wt, *wqkv, *bqkv, *vmean, *abase, *ctxl, *hl, *al, *midl;
    cudaGetSymbolAddress((void**)&h,     g_h);
    cudaGetSymbolAddress((void**)&a,     g_a);
    cudaGetSymbolAddress((void**)&qkv,   g_qkv);
    cudaGetSymbolAddress((void**)&mid,   g_mid);
    cudaGetSymbolAddress((void**)&y,     g_y);
    cudaGetSymbolAddress((void**)&wt,    g_wt);
    cudaGetSymbolAddress((void**)&wqkv,  g_wqkv);
    cudaGetSymbolAddress((void**)&bqkv,  g_bqkv);
    cudaGetSymbolAddress((void**)&vmean, g_vmean);
    cudaGetSymbolAddress((void**)&abase, g_abase);
    cudaGetSymbolAddress((void**)&ctxl,  g_ctxl);
    cudaGetSymbolAddress((void**)&hl,    g_hl);
    cudaGetSymbolAddress((void**)&al,    g_al);
    cudaGetSymbolAddress((void**)&midl,  g_midl);

    embed_kernel<<<BB * L0D, 256>>>(x, in_w, in_b, pos);

    int L = L0D;
    for (int i = 0; i < 3; i++) {
        int N = BB * L;
        int lshift = (L == 4096) ? 12 : (L == 2048) ? 11 : 10;
        dim3 blk(256);
        dim3 gQKV(QKVP / 128, N / 128);
        dim3 gD(DD / 128, N / 128);
        dim3 gF(FFD / 128, N / 128);

        // fused QKV projection (tf32)
        qkvcat_kernel<<<(DD * QKVP) / 256, 256>>>(qw + (size_t)i * DD * DD, kw + (size_t)i * DD * DD,
                                                  vw + (size_t)i * DD * DD, qb + i * DD, kb + i * DD, vb + i * DD);
        mm_kernel<0><<<gQKV, blk, SMEMSZ>>>(h, wqkv, bqkv, qkv, N, DD, QKVP, 0, L, lshift);

        // ProbSparse selection
        scoresM_kernel<<<BB * HD * (L / 256), 256>>>(idx[i], u[i], L);
        topk_kernel<<<BB * HD, 256>>>(u[i], L);
        vmean_kernel<<<BB * HD, 256>>>(L);

        // selection table
        seltclr_kernel<<<(BB * L + 255) / 256, 256>>>(BB * L);
        seltset_kernel<<<(BB * HD * u[i] + 255) / 256, 256>>>(u[i], L);

        // flash attention -> dctx
        flash_kernel<<<BB * HD, 256>>>(u[i], L);

        if (i < 2) {
            // attn output base: abase[b] = vmean[b] @ wo + ob (16 rows, fp32)
            rowgemm_kernel<<<BB, 256>>>(vmean, DD, ow + (size_t)i * DD * DD, ob + i * DD, abase, DD, DD, 0);
            // fused residual + base + sparse correction + LN1
            addln1f_kernel<<<N, 256>>>(h, ow + (size_t)i * DD * DD, n1g + i * DD, n1b + i * DD, h, L, lshift);
            // FFN
            mm_kernel<0><<<gF, blk, SMEMSZ>>>(h, f1w + (size_t)i * DD * FFD, f1b + i * FFD, mid, N, DD, FFD, 1, L, lshift);
            mm_kernel<0><<<gD, blk, SMEMSZ>>>(mid, f2w + (size_t)i * FFD * DD, f2b + i * DD, a, N, FFD, DD, 0, L, lshift);
            addln_kernel<<<N, 256>>>(h, a, n2g + i * DD, n2b + i * DD, h);
            // distill: conv k=3 implicit GEMM + pool + ELU
            wtrans_kernel<<<(DD * DD * 3) / 256, 256>>>(cw + (size_t)i * DD * DD * 3);
            mm_kernel<1><<<gD, blk, SMEMSZ>>>(h, wt, cb + i * DD, y, N, 768, DD, 0, L, lshift);
            pool_kernel<<<BB * (L / 2), 256>>>(L / 2);
            L /= 2;
        } else {
            // last layer: only the final position matters downstream
            size_t lastOff = (size_t)(L - 1) * DD;
            size_t pitch = (size_t)L * DD;
            ctxlast_kernel<<<BB, 256>>>(L);
            rowgemm_kernel<<<BB, 256>>>(ctxl, DD, ow + (size_t)i * DD * DD, ob + i * DD, al, DD, DD, 0);
            addln_last<<<BB, 256>>>(h + lastOff, pitch, al, n1g + i * DD, n1b + i * DD, hl);
            rowgemm_kernel<<<BB, 256>>>(hl, DD, f1w + (size_t)i * DD * FFD, f1b + i * FFD, midl, DD, FFD, 1);
            rowgemm_kernel<<<BB, 256>>>(midl, FFD, f2w + (size_t)i * FFD * DD, f2b + i * DD, al, FFD, DD, 0);
            addln_last<<<BB, 256>>>(hl, DD, al, n2g + i * DD, n2b + i * DD, hl);
        }
    }

    fc_kernel<<<BB, 32>>>(fcw, fcb, (float*)d_out);
}

// round 6
// speedup vs baseline: 3.6441x; 1.0014x over previous
#include <cuda_runtime.h>
#include <math.h>

// ---------------- problem constants ----------------
#define BB    16
#define L0D   4096
#define IND   8
#define DD    256
#define HD    8
#define DK    32
#define FFD   1024
#define PREDD 24
#define UMAX  64
#define QKVP  768
#define SCALE 0.17677669529663687f  // 1/sqrt(32)

// GEMM tile config: 128x128 tile, BK=16, double buffered
#define ASTR 20
#define BSTR 136
#define ASZ (128*ASTR)   // 2560 floats
#define BSZ (16*BSTR)    // 2176 floats
#define SMEMSZ ((ASZ+BSZ)*2*4)   // 37888 bytes < 48KB

// ---------------- scratch (device globals; no allocs allowed) ----------------
__device__ float g_h  [BB*L0D*DD];
__device__ float g_a  [BB*L0D*DD];
__device__ float g_qkv[BB*L0D*QKVP];
__device__ float g_mid[BB*L0D*FFD];
__device__ float g_y  [BB*L0D*DD];
__device__ float g_M  [BB*HD*L0D];
__device__ int   g_top[BB*HD*UMAX];
__device__ float g_dctx[BB*HD*UMAX*DK];
__device__ float g_vmean[BB*DD];
__device__ float g_wt [3*DD*DD];
__device__ float g_wqkv[DD*QKVP];
__device__ float g_bqkv[QKVP];
__device__ long long g_sel8[BB*L0D];      // per (b,l): 8 bytes, one per head: t or -1
__device__ float g_abase[BB*DD];
__device__ float g_ctxl[BB*DD];
__device__ float g_hl [BB*DD];
__device__ float g_al [BB*DD];
__device__ float g_midl[BB*FFD];

__device__ __forceinline__ float tf32f(float x) {
    unsigned u;
    asm("cvt.rna.tf32.f32 %0, %1;" : "=r"(u) : "f"(x));
    return __uint_as_float(u);
}

__device__ __forceinline__ float gelu_f(float v) {
    return 0.5f * v * (1.0f + erff(v * 0.70710678118654752f));
}

// ---------------- embed: h = x @ in_w + in_b + pos ----------------
__global__ void embed_kernel(const float* __restrict__ x, const float* __restrict__ in_w,
                             const float* __restrict__ in_b, const float* __restrict__ pos)
{
    int row = blockIdx.x;            // b*L0 + l
    int d   = threadIdx.x;
    int l   = row & (L0D - 1);
    const float* xr = x + (size_t)row * IND;
    float acc = in_b[d] + pos[(size_t)l * DD + d];
#pragma unroll
    for (int i = 0; i < IND; i++) acc += xr[i] * in_w[i * DD + d];
    g_h[(size_t)row * DD + d] = acc;
}

// ---------------- QKV weight/bias concat: g_wqkv[256][768] ----------------
__global__ void qkvcat_kernel(const float* __restrict__ qw, const float* __restrict__ kw,
                              const float* __restrict__ vw, const float* __restrict__ qb,
                              const float* __restrict__ kb, const float* __restrict__ vb)
{
    int e = blockIdx.x * 256 + threadIdx.x;     // over 256*768
    int k = e / QKVP, c = e % QKVP;
    float w = (c < 256) ? qw[k * DD + c] : (c < 512) ? kw[k * DD + c - 256] : vw[k * DD + c - 512];
    g_wqkv[e] = w;
    if (k == 0) g_bqkv[c] = (c < 256) ? qb[c] : (c < 512) ? kb[c - 256] : vb[c - 512];
}

// ---------------- TF32 tensor-core GEMM: Y = act(X[N,K] @ W[K,M] + bias) ----------------
// 128x128 tile, BK=16, 8 warps, double buffered, target 2 CTAs/SM.
// CONV=1: X is virtual im2col of Hin[B,L,256], k=3, pad=1 -> K=768.
template<int CONV>
__global__ __launch_bounds__(256, 2)
void mm_kernel(const float* __restrict__ X, const float* __restrict__ W,
               const float* __restrict__ bias, float* __restrict__ Y,
               int N, int K, int M, int act, int L, int lshift)
{
    extern __shared__ float smem[];
    float* As = smem;            // 2 * ASZ
    float* Bs = smem + 2 * ASZ;  // 2 * BSZ

    int tid  = threadIdx.x;
    int lane = tid & 31, wid = tid >> 5;
    int row0 = blockIdx.y * 128, col0 = blockIdx.x * 128;
    int wr = (wid & 3) * 32;
    int wc = (wid >> 2) * 64;
    int g  = lane >> 2, tg = lane & 3;

    float acc[2][8][4] = {};
    float4 ra[2], rb[2];

    int tiles = K >> 4;

    auto FETCH = [&](int kt) {
        int k0 = kt * 16;
#pragma unroll
        for (int i = 0; i < 2; i++) {
            int e = tid + i * 256;
            int r = e >> 2, c = (e & 3) * 4;
            if (!CONV) {
                ra[i] = *(const float4*)(X + (size_t)(row0 + r) * K + k0 + c);
            } else {
                int gk = k0 + c;
                int ksh = gk >> 8, ci = gk & 255;
                int gr = row0 + r;
                int b2 = gr >> lshift, t = gr & (L - 1);
                int tt = t + ksh - 1;
                if (tt >= 0 && tt < L)
                    ra[i] = *(const float4*)(X + ((size_t)(b2 << lshift) + tt) * DD + ci);
                else
                    ra[i] = make_float4(0.f, 0.f, 0.f, 0.f);
            }
            int r2 = e >> 5, c2 = (e & 31) * 4;
            rb[i] = *(const float4*)(W + (size_t)(k0 + r2) * M + col0 + c2);
        }
    };
    auto STORE = [&](int buf) {
        float* Ab = As + buf * ASZ;
        float* Bb = Bs + buf * BSZ;
#pragma unroll
        for (int i = 0; i < 2; i++) {
            int e = tid + i * 256;
            int r = e >> 2, c = (e & 3) * 4;
            float4 va = ra[i];
            va.x = tf32f(va.x); va.y = tf32f(va.y); va.z = tf32f(va.z); va.w = tf32f(va.w);
            *(float4*)(Ab + r * ASTR + c) = va;
            int r2 = e >> 5, c2 = (e & 31) * 4;
            float4 vb = rb[i];
            vb.x = tf32f(vb.x); vb.y = tf32f(vb.y); vb.z = tf32f(vb.z); vb.w = tf32f(vb.w);
            *(float4*)(Bb + r2 * BSTR + c2) = vb;
        }
    };

    FETCH(0);
    STORE(0);
    __syncthreads();

    for (int kt = 0; kt < tiles; kt++) {
        int cur = kt & 1;
        bool pf = (kt + 1 < tiles);
        if (pf) FETCH(kt + 1);

        const float* Ab = As + cur * ASZ;
        const float* Bb = Bs + cur * BSZ;
#pragma unroll
        for (int ks = 0; ks < 2; ks++) {
            unsigned af[2][4], bf[8][2];
#pragma unroll
            for (int mt = 0; mt < 2; mt++) {
                const float* ap = Ab + (wr + mt * 16 + g) * ASTR + ks * 8 + tg;
                af[mt][0] = __float_as_uint(ap[0]);
                af[mt][1] = __float_as_uint(ap[8 * ASTR]);
                af[mt][2] = __float_as_uint(ap[4]);
                af[mt][3] = __float_as_uint(ap[8 * ASTR + 4]);
            }
#pragma unroll
            for (int nt = 0; nt < 8; nt++) {
                const float* bp = Bb + (ks * 8 + tg) * BSTR + wc + nt * 8 + g;
                bf[nt][0] = __float_as_uint(bp[0]);
                bf[nt][1] = __float_as_uint(bp[4 * BSTR]);
            }
#pragma unroll
            for (int mt = 0; mt < 2; mt++)
#pragma unroll
                for (int nt = 0; nt < 8; nt++) {
                    asm volatile(
                        "mma.sync.aligned.m16n8k8.row.col.f32.tf32.tf32.f32 "
                        "{%0,%1,%2,%3},{%4,%5,%6,%7},{%8,%9},{%0,%1,%2,%3};\n"
                        : "+f"(acc[mt][nt][0]), "+f"(acc[mt][nt][1]),
                          "+f"(acc[mt][nt][2]), "+f"(acc[mt][nt][3])
                        : "r"(af[mt][0]), "r"(af[mt][1]), "r"(af[mt][2]), "r"(af[mt][3]),
                          "r"(bf[nt][0]), "r"(bf[nt][1]));
                }
        }
        if (pf) STORE(cur ^ 1);
        __syncthreads();
    }

#pragma unroll
    for (int mt = 0; mt < 2; mt++) {
#pragma unroll
        for (int nt = 0; nt < 8; nt++) {
            int r = row0 + wr + mt * 16 + g;
            int c = col0 + wc + nt * 8 + 2 * tg;
            float b0 = bias[c], b1 = bias[c + 1];
            float v0 = acc[mt][nt][0] + b0;
            float v1 = acc[mt][nt][1] + b1;
            float v2 = acc[mt][nt][2] + b0;
            float v3 = acc[mt][nt][3] + b1;
            if (act == 1) { v0 = gelu_f(v0); v1 = gelu_f(v1); v2 = gelu_f(v2); v3 = gelu_f(v3); }
            *(float2*)(Y + (size_t)r * M + c)       = make_float2(v0, v1);
            *(float2*)(Y + (size_t)(r + 8) * M + c) = make_float2(v2, v3);
        }
    }
}

// Wt[(k*256+ci)*256 + co] = cw[co, ci, k]
__global__ void wtrans_kernel(const float* __restrict__ cw)
{
    int e = blockIdx.x * 256 + threadIdx.x;
    int co = e / (DD * 3);
    int rem = e % (DD * 3);
    int ci = rem / 3, k = rem % 3;
    g_wt[((size_t)(k * DD + ci)) * DD + co] = cw[e];
}

// ---------------- sparse scores + M = max - mean over u sampled keys ----------------
__global__ void scoresM_kernel(const int* __restrict__ idx, int u, int L)
{
    int chunks = L >> 8;
    int bh = blockIdx.x / chunks;
    int l0 = (blockIdx.x % chunks) << 8;
    int b = bh >> 3, hh = bh & 7;
    __shared__ float sk[UMAX * DK];
    for (int e = threadIdx.x; e < u * DK; e += 256) {
        int t = e >> 5, j = e & 31;
        sk[e] = g_qkv[((size_t)b * L + idx[t]) * QKVP + 256 + hh * DK + j];
    }
    __syncthreads();
    int l = l0 + threadIdx.x;
    const float* qr = g_qkv + ((size_t)b * L + l) * QKVP + hh * DK;
    float q[DK];
#pragma unroll
    for (int j = 0; j < DK; j++) q[j] = qr[j];
    float mx = -INFINITY, sm = 0.f;
    for (int t = 0; t < u; t++) {
        float dot = 0.f;
#pragma unroll
        for (int j = 0; j < DK; j++) dot += q[j] * sk[t * DK + j];
        dot *= SCALE;
        mx = fmaxf(mx, dot);
        sm += dot;
    }
    g_M[(size_t)bh * L + l] = mx - sm / (float)u;
}

// ---------------- top-u selection per (b,h); ties -> lowest index ----------------
__global__ void topk_kernel(int u, int L)
{
    int bh = blockIdx.x;
    __shared__ float sm[L0D];
    __shared__ float rv[256];
    __shared__ int   ri[256];
    int tid = threadIdx.x;
    for (int l = tid; l < L; l += 256) sm[l] = g_M[(size_t)bh * L + l];
    __syncthreads();
    for (int t = 0; t < u; t++) {
        float best = -INFINITY; int bi = 0x7fffffff;
        for (int l = tid; l < L; l += 256) {
            float v = sm[l];
            if (v > best || (v == best && l < bi)) { best = v; bi = l; }
        }
        rv[tid] = best; ri[tid] = bi;
        __syncthreads();
        for (int s = 128; s > 0; s >>= 1) {
            if (tid < s) {
                float v2 = rv[tid + s]; int i2 = ri[tid + s];
                if (v2 > rv[tid] || (v2 == rv[tid] && i2 < ri[tid])) { rv[tid] = v2; ri[tid] = i2; }
            }
            __syncthreads();
        }
        if (tid == 0) { g_top[bh * UMAX + t] = ri[0]; sm[ri[0]] = -INFINITY; }
        __syncthreads();
    }
}

// ---------------- V mean over L per (b,h,dk) ----------------
__global__ void vmean_kernel(int L)
{
    int bh = blockIdx.x;
    int b = bh >> 3, hh = bh & 7;
    int tid = threadIdx.x;
    int d = tid & 31, c = tid >> 5;
    int chunk = L >> 3;
    float s = 0.f;
    for (int l = c * chunk; l < (c + 1) * chunk; l++)
        s += g_qkv[((size_t)b * L + l) * QKVP + 512 + hh * DK + d];
    __shared__ float part[8][DK];
    part[c][d] = s;
    __syncthreads();
    if (tid < DK) {
        float tot = 0.f;
#pragma unroll
        for (int cc = 0; cc < 8; cc++) tot += part[cc][d];
        g_vmean[b * DD + hh * DK + d] = tot / (float)L;
    }
}

// ---------------- selection table: per (b,l,h) -> t or -1 ----------------
__global__ void seltclr_kernel(int n)
{
    int e = blockIdx.x * 256 + threadIdx.x;
    if (e < n) g_sel8[e] = -1LL;
}

__global__ void seltset_kernel(int u, int L)
{
    int e = blockIdx.x * 256 + threadIdx.x;   // over B*H*u
    if (e >= BB * HD * u) return;
    int t = e % u, bh = e / u;
    int b = bh >> 3, hh = bh & 7;
    int l = g_top[bh * UMAX + t];
    ((signed char*)g_sel8)[((size_t)b * L + l) * 8 + hh] = (signed char)t;
}

// ---------------- flash attention for top-u queries -> dctx = ctx_top - vmean_slice ----------------
#define KSTR 33
__global__ __launch_bounds__(256)
void flash_kernel(int u, int L)
{
    int bh = blockIdx.x;
    int b = bh >> 3, hh = bh & 7;
    int tid = threadIdx.x, lane = tid & 31, wid = tid >> 5;
    __shared__ float sq[48 * 32];
    __shared__ float Ks[128 * KSTR];
    __shared__ float Vs[128 * KSTR];

    for (int e = tid; e < u * 32; e += 256) {
        int t = e >> 5, j = e & 31;
        int qi = g_top[bh * UMAX + t];
        sq[e] = g_qkv[((size_t)b * L + qi) * QKVP + hh * DK + j];
    }

    float m[6], s[6], av[6];
#pragma unroll
    for (int i = 0; i < 6; i++) { m[i] = -INFINITY; s[i] = 0.f; av[i] = 0.f; }

    int chunks = L >> 7;
    for (int c0 = 0; c0 < chunks; c0++) {
        __syncthreads();
#pragma unroll
        for (int i = 0; i < 4; i++) {
            int e = tid + i * 256;
            int r = e >> 3, c = (e & 7) * 4;
            const float* base = g_qkv + ((size_t)b * L + (c0 << 7) + r) * QKVP + hh * DK + c;
            float4 kf = *(const float4*)(base + 256);
            float4 vf = *(const float4*)(base + 512);
            float* kd = Ks + r * KSTR + c;
            kd[0] = kf.x; kd[1] = kf.y; kd[2] = kf.z; kd[3] = kf.w;
            float* vd = Vs + r * KSTR + c;
            vd[0] = vf.x; vd[1] = vf.y; vd[2] = vf.z; vd[3] = vf.w;
        }
        __syncthreads();

#pragma unroll
        for (int ti = 0; ti < 6; ti++) {
            int t = wid + ti * 8;
            if (t >= u) continue;
            float sc[4];
#pragma unroll
            for (int sub = 0; sub < 4; sub++) {
                const float* kr = Ks + (sub * 32 + lane) * KSTR;
                const float* qv = sq + t * 32;
                float dot = 0.f;
#pragma unroll
                for (int j = 0; j < 32; j++) dot += qv[j] * kr[j];
                sc[sub] = dot * SCALE;
            }
            float cm = fmaxf(fmaxf(sc[0], sc[1]), fmaxf(sc[2], sc[3]));
#pragma unroll
            for (int o = 16; o > 0; o >>= 1) cm = fmaxf(cm, __shfl_xor_sync(0xffffffffu, cm, o));
            float mn = fmaxf(m[ti], cm);
            float corr = expf(m[ti] - mn);
            m[ti] = mn;
            float p[4]; float ps = 0.f;
#pragma unroll
            for (int sub = 0; sub < 4; sub++) { p[sub] = expf(sc[sub] - mn); ps += p[sub]; }
#pragma unroll
            for (int o = 16; o > 0; o >>= 1) ps += __shfl_xor_sync(0xffffffffu, ps, o);
            s[ti] = s[ti] * corr + ps;
            float a = av[ti] * corr;
#pragma unroll
            for (int sub = 0; sub < 4; sub++)
#pragma unroll
                for (int kk = 0; kk < 32; kk++) {
                    float pv = __shfl_sync(0xffffffffu, p[sub], kk);
                    a += pv * Vs[(sub * 32 + kk) * KSTR + lane];
                }
            av[ti] = a;
        }
    }

    float vm = g_vmean[b * DD + hh * DK + lane];
#pragma unroll
    for (int ti = 0; ti < 6; ti++) {
        int t = wid + ti * 8;
        if (t < u)
            g_dctx[((size_t)bh * UMAX + t) * DK + lane] = av[ti] / s[ti] - vm;
    }
}

// ---------------- fused residual + attn-base + sparse correction + LayerNorm ----------------
__global__ void addln1f_kernel(const float* __restrict__ h, const float* __restrict__ wo,
                               const float* __restrict__ g, const float* __restrict__ bb,
                               float* __restrict__ out, int L, int lshift)
{
    int row = blockIdx.x;
    int b = row >> lshift, l = row & (L - 1);
    int d = threadIdx.x;
    float x = h[(size_t)row * DD + d] + g_abase[b * DD + d];
    long long sv = g_sel8[(size_t)b * L + l];
    if (sv != -1LL) {
#pragma unroll
        for (int hh = 0; hh < 8; hh++) {
            int t = (int)(signed char)(sv >> (hh * 8));
            if (t >= 0) {
                const float* dc = g_dctx + ((size_t)(b * 8 + hh) * UMAX + t) * DK;
                const float* wr = wo + (size_t)hh * 32 * DD + d;
#pragma unroll
                for (int j = 0; j < 32; j++) x += dc[j] * wr[(size_t)j * DD];
            }
        }
    }
    __shared__ float red[256];
    red[d] = x; __syncthreads();
    for (int st = 128; st > 0; st >>= 1) { if (d < st) red[d] += red[d + st]; __syncthreads(); }
    float mval = red[0] * (1.f / DD);
    __syncthreads();
    float xm = x - mval;
    red[d] = xm * xm; __syncthreads();
    for (int st = 128; st > 0; st >>= 1) { if (d < st) red[d] += red[d + st]; __syncthreads(); }
    float v = red[0] * (1.f / DD);
    out[(size_t)row * DD + d] = xm * rsqrtf(v + 1e-5f) * g[d] + bb[d];
}

// ---------------- residual + LayerNorm ----------------
__global__ void addln_kernel(const float* __restrict__ A, const float* __restrict__ Bt,
                             const float* __restrict__ g, const float* __restrict__ bb,
                             float* __restrict__ out)
{
    size_t row = blockIdx.x;
    int d = threadIdx.x;
    float x = A[row * DD + d] + Bt[row * DD + d];
    __shared__ float red[256];
    red[d] = x; __syncthreads();
    for (int s = 128; s > 0; s >>= 1) { if (d < s) red[d] += red[d + s]; __syncthreads(); }
    float m = red[0] * (1.f / DD);
    __syncthreads();
    float xm = x - m;
    red[d] = xm * xm; __syncthreads();
    for (int s = 128; s > 0; s >>= 1) { if (d < s) red[d] += red[d + s]; __syncthreads(); }
    float v = red[0] * (1.f / DD);
    out[row * DD + d] = xm * rsqrtf(v + 1e-5f) * g[d] + bb[d];
}

// last-row variant
__global__ void addln_last(const float* __restrict__ A, size_t pitchA,
                           const float* __restrict__ Bt,
                           const float* __restrict__ g, const float* __restrict__ bb,
                           float* __restrict__ out)
{
    int b = blockIdx.x;
    int d = threadIdx.x;
    float x = A[(size_t)b * pitchA + d] + Bt[(size_t)b * DD + d];
    __shared__ float red[256];
    red[d] = x; __syncthreads();
    for (int s = 128; s > 0; s >>= 1) { if (d < s) red[d] += red[d + s]; __syncthreads(); }
    float m = red[0] * (1.f / DD);
    __syncthreads();
    float xm = x - m;
    red[d] = xm * xm; __syncthreads();
    for (int s = 128; s > 0; s >>= 1) { if (d < s) red[d] += red[d + s]; __syncthreads(); }
    float v = red[0] * (1.f / DD);
    out[(size_t)b * DD + d] = xm * rsqrtf(v + 1e-5f) * g[d] + bb[d];
}

// ---------------- last-layer ctx row (l = L-1) ----------------
__global__ void ctxlast_kernel(int L)
{
    int b = blockIdx.x, d = threadIdx.x;
    float val = g_vmean[b * DD + d];
    int hh = d >> 5, j = d & 31;
    signed char t = ((const signed char*)g_sel8)[((size_t)b * L + (L - 1)) * 8 + hh];
    if (t >= 0) val += g_dctx[((size_t)(b * 8 + hh) * UMAX + (int)t) * DK + j];
    g_ctxl[b * DD + d] = val;
}

// ---------------- small per-batch-row GEMM (16 rows) ----------------
__global__ void rowgemm_kernel(const float* __restrict__ X, size_t xPitch,
                               const float* __restrict__ W, const float* __restrict__ bias,
                               float* __restrict__ Y, int K, int M, int act)
{
    int b = blockIdx.x;
    __shared__ float xs[FFD];
    const float* xr = X + (size_t)b * xPitch;
    for (int i = threadIdx.x; i < K; i += 256) xs[i] = xr[i];
    __syncthreads();
    for (int c = threadIdx.x; c < M; c += 256) {
        float acc = bias[c];
        for (int kk = 0; kk < K; kk++) acc += xs[kk] * W[(size_t)kk * M + c];
        if (act == 1) acc = gelu_f(acc);
        Y[(size_t)b * M + c] = acc;
    }
}

// ---------------- maxpool(2) + ELU ----------------
__global__ void pool_kernel(int Lnew)
{
    int r = blockIdx.x;
    int b = r / Lnew, j = r % Lnew;
    int d = threadIdx.x;
    int L = Lnew * 2;
    float y0 = g_y[((size_t)b * L + 2 * j    ) * DD + d];
    float y1 = g_y[((size_t)b * L + 2 * j + 1) * DD + d];
    float m = fmaxf(y0, y1);
    g_h[(size_t)r * DD + d] = (m > 0.f) ? m : expm1f(m);
}

// ---------------- final FC ----------------
__global__ void fc_kernel(const float* __restrict__ fcw, const float* __restrict__ fcb,
                          float* __restrict__ out)
{
    int b = blockIdx.x;
    int p = threadIdx.x;
    if (p >= PREDD) return;
    const float* hr = g_hl + (size_t)b * DD;
    float acc = fcb[p];
    for (int d = 0; d < DD; d++) acc += hr[d] * fcw[d * PREDD + p];
    out[b * PREDD + p] = acc;
}

// ---------------- host orchestration ----------------
extern "C" void kernel_launch(void* const* d_in, const int* in_sizes, int n_in,
                              void* d_out, int out_size)
{
    const float* x    = (const float*)d_in[0];
    const int*   idx[3] = { (const int*)d_in[1], (const int*)d_in[2], (const int*)d_in[3] };
    int          u[3]   = { in_sizes[1], in_sizes[2], in_sizes[3] };
    const float* in_w = (const float*)d_in[4];
    const float* in_b = (const float*)d_in[5];
    const float* pos  = (const float*)d_in[6];
    const float* qw = (const float*)d_in[7];  const float* qb = (const float*)d_in[8];
    const float* kw = (const float*)d_in[9];  const float* kb = (const float*)d_in[10];
    const float* vw = (const float*)d_in[11]; const float* vb = (const float*)d_in[12];
    const float* ow = (const float*)d_in[13]; const float* ob = (const float*)d_in[14];
    const float* f1w = (const float*)d_in[15]; const float* f1b = (const float*)d_in[16];
    const float* f2w = (const float*)d_in[17]; const float* f2b = (const float*)d_in[18];
    const float* n1g = (const float*)d_in[19]; const float* n1b = (const float*)d_in[20];
    const float* n2g = (const float*)d_in[21]; const float* n2b = (const float*)d_in[22];
    const float* cw  = (const float*)d_in[23]; const float* cb  = (const float*)d_in[24];
    const float* fcw = (const float*)d_in[25]; const float* fcb = (const float*)d_in[26];

    float *h, *a, *qkv, *mid, *y, *wt, *wqkv, *bqkv, *vmean, *abase, *ctxl, *hl, *al, *midl;
    cudaGetSymbolAddress((void**)&h,     g_h);
    cudaGetSymbolAddress((void**)&a,     g_a);
    cudaGetSymbolAddress((void**)&qkv,   g_qkv);
    cudaGetSymbolAddress((void**)&mid,   g_mid);
    cudaGetSymbolAddress((void**)&y,     g_y);
    cudaGetSymbolAddress((void**)&wt,    g_wt);
    cudaGetSymbolAddress((void**)&wqkv,  g_wqkv);
    cudaGetSymbolAddress((void**)&bqkv,  g_bqkv);
    cudaGetSymbolAddress((void**)&vmean, g_vmean);
    cudaGetSymbolAddress((void**)&abase, g_abase);
    cudaGetSymbolAddress((void**)&ctxl,  g_ctxl);
    cudaGetSymbolAddress((void**)&hl,    g_hl);
    cudaGetSymbolAddress((void**)&al,    g_al);
    cudaGetSymbolAddress((void**)&midl,  g_midl);

    embed_kernel<<<BB * L0D, 256>>>(x, in_w, in_b, pos);

    int L = L0D;
    for (int i = 0; i < 3; i++) {
        int N = BB * L;
        int lshift = (L == 4096) ? 12 : (L == 2048) ? 11 : 10;
        dim3 blk(256);
        dim3 gQKV(QKVP / 128, N / 128);
        dim3 gD(DD / 128, N / 128);
        dim3 gF(FFD / 128, N / 128);

        // fused QKV projection (tf32)
        qkvcat_kernel<<<(DD * QKVP) / 256, 256>>>(qw + (size_t)i * DD * DD, kw + (size_t)i * DD * DD,
                                                  vw + (size_t)i * DD * DD, qb + i * DD, kb + i * DD, vb + i * DD);
        mm_kernel<0><<<gQKV, blk, SMEMSZ>>>(h, wqkv, bqkv, qkv, N, DD, QKVP, 0, L, lshift);

        // ProbSparse selection
        scoresM_kernel<<<BB * HD * (L / 256), 256>>>(idx[i], u[i], L);
        topk_kernel<<<BB * HD, 256>>>(u[i], L);
        vmean_kernel<<<BB * HD, 256>>>(L);

        // selection table
        seltclr_kernel<<<(BB * L + 255) / 256, 256>>>(BB * L);
        seltset_kernel<<<(BB * HD * u[i] + 255) / 256, 256>>>(u[i], L);

        // flash attention -> dctx
        flash_kernel<<<BB * HD, 256>>>(u[i], L);

        if (i < 2) {
            // attn output base: abase[b] = vmean[b] @ wo + ob (16 rows, fp32)
            rowgemm_kernel<<<BB, 256>>>(vmean, DD, ow + (size_t)i * DD * DD, ob + i * DD, abase, DD, DD, 0);
            // fused residual + base + sparse correction + LN1
            addln1f_kernel<<<N, 256>>>(h, ow + (size_t)i * DD * DD, n1g + i * DD, n1b + i * DD, h, L, lshift);
            // FFN
            mm_kernel<0><<<gF, blk, SMEMSZ>>>(h, f1w + (size_t)i * DD * FFD, f1b + i * FFD, mid, N, DD, FFD, 1, L, lshift);
            mm_kernel<0><<<gD, blk, SMEMSZ>>>(mid, f2w + (size_t)i * FFD * DD, f2b + i * DD, a, N, FFD, DD, 0, L, lshift);
            addln_kernel<<<N, 256>>>(h, a, n2g + i * DD, n2b + i * DD, h);
            // distill: conv k=3 implicit GEMM + pool + ELU
            wtrans_kernel<<<(DD * DD * 3) / 256, 256>>>(cw + (size_t)i * DD * DD * 3);
            mm_kernel<1><<<gD, blk, SMEMSZ>>>(h, wt, cb + i * DD, y, N, 768, DD, 0, L, lshift);
            pool_kernel<<<BB * (L / 2), 256>>>(L / 2);
            L /= 2;
        } else {
            // last layer: only the final position matters downstream
            size_t lastOff = (size_t)(L - 1) * DD;
            size_t pitch = (size_t)L * DD;
            ctxlast_kernel<<<BB, 256>>>(L);
            rowgemm_kernel<<<BB, 256>>>(ctxl, DD, ow + (size_t)i * DD * DD, ob + i * DD, al, DD, DD, 0);
            addln_last<<<BB, 256>>>(h + lastOff, pitch, al, n1g + i * DD, n1b + i * DD, hl);
            rowgemm_kernel<<<BB, 256>>>(hl, DD, f1w + (size_t)i * DD * FFD, f1b + i * FFD, midl, DD, FFD, 1);
            rowgemm_kernel<<<BB, 256>>>(midl, FFD, f2w + (size_t)i * FFD * DD, f2b + i * DD, al, FFD, DD, 0);
            addln_last<<<BB, 256>>>(hl, DD, al, n2g + i * DD, n2b + i * DD, hl);
        }
    }

    fc_kernel<<<BB, 32>>>(fcw, fcb, (float*)d_out);
}